// round 2
// baseline (speedup 1.0000x reference)
#include <cuda_runtime.h>

#define NA 60000
#define NBOND 120000
#define MAXNB 6
#define HID 512
#define AF 133
#define BF 147
#define NM 512

// ---------------- scratch (device globals; no allocations allowed) ----------
__device__ float g_inp[(size_t)NBOND * HID];   // pre-relu input features per bond
__device__ float g_msg[(size_t)NBOND * HID];   // current bond message
__device__ float g_tmp[(size_t)NBOND * HID];   // pre-GEMM directed message
__device__ float g_amsg[(size_t)NA * HID];     // per-atom summed message
__device__ float g_ah[(size_t)NA * HID];       // atom hiddens
__device__ float g_sums[NM * HID];
__device__ float g_cnt[NM];
__device__ int   g_a2b[NA * MAXNB];
__device__ int   g_b2a[NBOND];
__device__ int   g_b2revb[NBOND];
__device__ int   g_mol[NA];
__device__ int   g_any32[4];   // 1 => buffer is int32, 0 => int64

// ---------------- index dtype detection + conversion ------------------------
// Scan the FIRST n 32-bit words of the buffer (safe for both dtypes: an int32
// buffer has exactly n words, an int64 buffer has 2n). If data is int64, every
// odd word is a high half == 0 (all values < 2^31). If int32, odd words hold
// real index values. Any nonzero odd word => int32.
__global__ void reset_flags_kernel() {
    if (threadIdx.x < 4) g_any32[threadIdx.x] = 0;
}

__global__ void scan_dtype_kernel(const unsigned* __restrict__ p, int nwords, int fi) {
    int i = blockIdx.x * blockDim.x + threadIdx.x;
    if (i >= nwords) return;
    if ((i & 1) && p[i] != 0u) atomicOr(&g_any32[fi], 1);
}

__global__ void convert_idx_kernel(const void* __restrict__ src, int* __restrict__ dst,
                                   int n, int fi) {
    int i = blockIdx.x * blockDim.x + threadIdx.x;
    if (i >= n) return;
    if (g_any32[fi]) dst[i] = ((const int*)src)[i];
    else             dst[i] = (int)((const long long*)src)[i];
}

// ---------------- SGEMM: C[M,N] = act( A @ W^T (+ addmat) (+ bias) ) --------
// A is [M,K] row-major (optionally a concat of A0[M,K0] and A1[M,HID]).
// W is [N,K] row-major. 128x128x16 tiles, 256 threads, 8x8 microtile.
#define BM 128
#define BN 128
#define BK 16

__device__ __forceinline__ float load_a(const float* __restrict__ A0, int K0,
                                        const float* __restrict__ A1,
                                        int m, int k, int K) {
    if (A1 == nullptr) return A0[(size_t)m * K + k];
    return (k < K0) ? A0[(size_t)m * K0 + k]
                    : A1[(size_t)m * HID + (k - K0)];
}

__global__ __launch_bounds__(256, 2)
void sgemm_kernel(const float* __restrict__ A0, int K0,
                  const float* __restrict__ A1,
                  const float* __restrict__ W,
                  const float* __restrict__ addmat,
                  const float* __restrict__ bias,
                  float* __restrict__ C,
                  float* __restrict__ C2,      // optional relu copy
                  int M, int N, int K, int relu_c) {
    __shared__ float As[BK][BM + 4];
    __shared__ float Bs[BK][BN + 4];

    const int t = threadIdx.x;
    const int tx = t & 15;        // 0..15 -> N microtile
    const int ty = t >> 4;        // 0..15 -> M microtile
    const int bm = blockIdx.y * BM;
    const int bn = blockIdx.x * BN;

    float acc[8][8];
    #pragma unroll
    for (int i = 0; i < 8; i++)
        #pragma unroll
        for (int j = 0; j < 8; j++) acc[i][j] = 0.f;

    for (int k0 = 0; k0 < K; k0 += BK) {
        // load A tile: 128 rows x 16 cols
        #pragma unroll
        for (int i = 0; i < 8; i++) {
            int e = i * 256 + t;
            int r = e >> 4, c = e & 15;
            int gm = bm + r, gk = k0 + c;
            float v = 0.f;
            if (gm < M && gk < K) v = load_a(A0, K0, A1, gm, gk, K);
            As[c][r] = v;
        }
        // load W tile: 128 N-rows x 16 k-cols
        #pragma unroll
        for (int i = 0; i < 8; i++) {
            int e = i * 256 + t;
            int r = e >> 4, c = e & 15;
            int gn = bn + r, gk = k0 + c;
            float v = 0.f;
            if (gn < N && gk < K) v = W[(size_t)gn * K + gk];
            Bs[c][r] = v;
        }
        __syncthreads();

        #pragma unroll
        for (int k = 0; k < BK; k++) {
            float a[8], b[8];
            #pragma unroll
            for (int i = 0; i < 8; i += 4) {
                float4 v = *(const float4*)&As[k][ty * 8 + i];
                a[i] = v.x; a[i+1] = v.y; a[i+2] = v.z; a[i+3] = v.w;
            }
            #pragma unroll
            for (int j = 0; j < 8; j += 4) {
                float4 v = *(const float4*)&Bs[k][tx * 8 + j];
                b[j] = v.x; b[j+1] = v.y; b[j+2] = v.z; b[j+3] = v.w;
            }
            #pragma unroll
            for (int i = 0; i < 8; i++)
                #pragma unroll
                for (int j = 0; j < 8; j++)
                    acc[i][j] += a[i] * b[j];
        }
        __syncthreads();
    }

    // epilogue
    #pragma unroll
    for (int i = 0; i < 8; i++) {
        int gm = bm + ty * 8 + i;
        if (gm >= M) continue;
        #pragma unroll
        for (int j = 0; j < 8; j++) {
            int gn = bn + tx * 8 + j;
            if (gn >= N) continue;
            float v = acc[i][j];
            if (bias)   v += bias[gn];
            if (addmat) v += addmat[(size_t)gm * N + gn];
            float r = v > 0.f ? v : 0.f;
            C[(size_t)gm * N + gn] = relu_c ? r : v;
            if (C2) C2[(size_t)gm * N + gn] = r;
        }
    }
}

// ---------------- gather / update kernels ------------------------------------
// a_message[a] = sum_j message[a2b[a][j]]
__global__ void gather_sum_kernel(const float* __restrict__ msg,
                                  float* __restrict__ amsg) {
    int idx = blockIdx.x * blockDim.x + threadIdx.x;
    const int h4 = HID / 4;                       // 128 float4 per row
    if (idx >= NA * h4) return;
    int a = idx / h4;
    int h = (idx - a * h4) * 4;
    float4 acc = make_float4(0.f, 0.f, 0.f, 0.f);
    #pragma unroll
    for (int j = 0; j < MAXNB; j++) {
        int b = g_a2b[a * MAXNB + j];
        float4 v = *(const float4*)(msg + (size_t)b * HID + h);
        acc.x += v.x; acc.y += v.y; acc.z += v.z; acc.w += v.w;
    }
    *(float4*)(amsg + (size_t)a * HID + h) = acc;
}

// tmp[b] = amsg[b2a[b]] - msg[b2revb[b]]
__global__ void bond_update_kernel(const float* __restrict__ amsg,
                                   const float* __restrict__ msg,
                                   float* __restrict__ tmp) {
    int idx = blockIdx.x * blockDim.x + threadIdx.x;
    const int h4 = HID / 4;
    if (idx >= NBOND * h4) return;
    int b = idx / h4;
    int h = (idx - b * h4) * 4;
    int sa = g_b2a[b];
    int rb = g_b2revb[b];
    float4 u = *(const float4*)(amsg + (size_t)sa * HID + h);
    float4 w = *(const float4*)(msg + (size_t)rb * HID + h);
    float4 o = make_float4(u.x - w.x, u.y - w.y, u.z - w.z, u.w - w.w);
    *(float4*)(tmp + (size_t)b * HID + h) = o;
}

// ---------------- pooling ----------------------------------------------------
__global__ void pool_zero_kernel() {
    int i = blockIdx.x * blockDim.x + threadIdx.x;
    if (i < NM * HID) g_sums[i] = 0.f;
    if (i < NM) g_cnt[i] = 0.f;
}

__global__ void pool_sum_kernel(const float* __restrict__ ah) {
    int idx = blockIdx.x * blockDim.x + threadIdx.x;
    const int h4 = HID / 4;
    if (idx >= NA * h4) return;
    int a = idx / h4;
    int h = (idx - a * h4) * 4;
    int m = g_mol[a];
    float4 v = *(const float4*)(ah + (size_t)a * HID + h);
    float* dst = g_sums + (size_t)m * HID + h;
    atomicAdd(dst + 0, v.x);
    atomicAdd(dst + 1, v.y);
    atomicAdd(dst + 2, v.z);
    atomicAdd(dst + 3, v.w);
}

__global__ void pool_count_kernel() {
    int a = blockIdx.x * blockDim.x + threadIdx.x;
    if (a >= NA) return;
    atomicAdd(&g_cnt[g_mol[a]], 1.f);
}

__global__ void finalize_kernel(float* __restrict__ out) {
    int i = blockIdx.x * blockDim.x + threadIdx.x;
    if (i >= NM * HID) return;
    float c = g_cnt[i / HID];
    out[i] = g_sums[i] / fmaxf(c, 1.f);
}

// ---------------- launch -----------------------------------------------------
extern "C" void kernel_launch(void* const* d_in, const int* in_sizes, int n_in,
                              void* d_out, int out_size) {
    const float* f_atoms = (const float*)d_in[0];
    const float* f_bonds = (const float*)d_in[1];
    const float* W_i     = (const float*)d_in[2];
    const float* W_h     = (const float*)d_in[3];
    const float* W_o     = (const float*)d_in[4];
    const float* b_o     = (const float*)d_in[5];
    const void*  a2b     = d_in[6];
    const void*  b2a     = d_in[7];
    const void*  b2revb  = d_in[8];
    const void*  mol     = d_in[9];
    float* out = (float*)d_out;

    int* d_a2b;    cudaGetSymbolAddress((void**)&d_a2b, g_a2b);
    int* d_b2a;    cudaGetSymbolAddress((void**)&d_b2a, g_b2a);
    int* d_b2revb; cudaGetSymbolAddress((void**)&d_b2revb, g_b2revb);
    int* d_mol;    cudaGetSymbolAddress((void**)&d_mol, g_mol);
    float* d_inp;  cudaGetSymbolAddress((void**)&d_inp, g_inp);
    float* d_msg;  cudaGetSymbolAddress((void**)&d_msg, g_msg);
    float* d_tmp;  cudaGetSymbolAddress((void**)&d_tmp, g_tmp);
    float* d_amsg; cudaGetSymbolAddress((void**)&d_amsg, g_amsg);
    float* d_ah;   cudaGetSymbolAddress((void**)&d_ah, g_ah);

    // 1) detect index dtype (int32 vs int64), then canonicalize to int32
    reset_flags_kernel<<<1, 32>>>();
    scan_dtype_kernel<<<(NA * MAXNB + 255) / 256, 256>>>((const unsigned*)a2b, NA * MAXNB, 0);
    scan_dtype_kernel<<<(NBOND + 255) / 256, 256>>>((const unsigned*)b2a, NBOND, 1);
    scan_dtype_kernel<<<(NBOND + 255) / 256, 256>>>((const unsigned*)b2revb, NBOND, 2);
    scan_dtype_kernel<<<(NA + 255) / 256, 256>>>((const unsigned*)mol, NA, 3);
    convert_idx_kernel<<<(NA * MAXNB + 255) / 256, 256>>>(a2b, d_a2b, NA * MAXNB, 0);
    convert_idx_kernel<<<(NBOND + 255) / 256, 256>>>(b2a, d_b2a, NBOND, 1);
    convert_idx_kernel<<<(NBOND + 255) / 256, 256>>>(b2revb, d_b2revb, NBOND, 2);
    convert_idx_kernel<<<(NA + 255) / 256, 256>>>(mol, d_mol, NA, 3);

    // 2) inp = f_bonds @ W_i^T ; msg = relu(inp)
    {
        dim3 grid((HID + BN - 1) / BN, (NBOND + BM - 1) / BM);
        sgemm_kernel<<<grid, 256>>>(f_bonds, BF, nullptr, W_i,
                                    nullptr, nullptr,
                                    d_inp, d_msg, NBOND, HID, BF, 0);
    }

    // 3) message passing iterations
    const int gthreads = 256;
    const int gblocks_a = (NA * (HID / 4) + gthreads - 1) / gthreads;
    const int gblocks_b = (NBOND * (HID / 4) + gthreads - 1) / gthreads;
    for (int it = 0; it < 4; it++) {
        gather_sum_kernel<<<gblocks_a, gthreads>>>(d_msg, d_amsg);
        bond_update_kernel<<<gblocks_b, gthreads>>>(d_amsg, d_msg, d_tmp);
        dim3 grid((HID + BN - 1) / BN, (NBOND + BM - 1) / BM);
        sgemm_kernel<<<grid, 256>>>(d_tmp, HID, nullptr, W_h,
                                    d_inp, nullptr,
                                    d_msg, nullptr, NBOND, HID, HID, 1);
    }

    // 4) final atom gather + output GEMM (concat A)
    gather_sum_kernel<<<gblocks_a, gthreads>>>(d_msg, d_amsg);
    {
        dim3 grid((HID + BN - 1) / BN, (NA + BM - 1) / BM);
        sgemm_kernel<<<grid, 256>>>(f_atoms, AF, d_amsg, W_o,
                                    nullptr, b_o,
                                    d_ah, nullptr, NA, HID, AF + HID, 1);
    }

    // 5) per-molecule mean pooling
    pool_zero_kernel<<<(NM * HID + 255) / 256, 256>>>();
    pool_sum_kernel<<<gblocks_a, gthreads>>>(d_ah);
    pool_count_kernel<<<(NA + 255) / 256, 256>>>();
    finalize_kernel<<<(NM * HID + 255) / 256, 256>>>(out);
}

// round 5
// speedup vs baseline: 1.7626x; 1.7626x over previous
#include <cuda_runtime.h>
#include <cuda_bf16.h>
#include <cstdint>

#define NA 60000
#define NBOND 120000
#define MAXNB 6
#define HID 512
#define AF 133
#define BF 147
#define NM 512

// ---------------- scratch (device globals; no allocations allowed) ----------
__device__ float g_inp[(size_t)NBOND * HID];
__device__ float g_msgA[(size_t)NBOND * HID];
__device__ float g_msgB[(size_t)NBOND * HID];
__device__ float g_amsg[(size_t)NA * HID];
__device__ float g_ah[(size_t)NA * HID];
__device__ float g_sums[NM * HID];
__device__ float g_cnt[NM];
__device__ int   g_a2b[NA * MAXNB];
__device__ int   g_b2a[NBOND];
__device__ int   g_b2revb[NBOND];
__device__ int   g_mol[NA];
__device__ int   g_any32[4];

// triple-split packed weights, per 16-k chunk: [hi(16) | hi(16) | lo(16)] halves
#define KP_WI 160   // ceil(147/16)*16
#define KP_WH 512
#define KP_WO 656   // ceil(645/16)*16
__device__ unsigned short g_Wi3[512 * KP_WI * 3];
__device__ unsigned short g_Wh3[512 * KP_WH * 3];
__device__ unsigned short g_Wo3[512 * KP_WO * 3];

// ---------------- small helpers ---------------------------------------------
__device__ __forceinline__ uint32_t smem_u32(const void* p) {
    uint32_t a;
    asm("{ .reg .u64 t; cvta.to.shared.u64 t, %1; cvt.u32.u64 %0, t; }" : "=r"(a) : "l"(p));
    return a;
}
__device__ __forceinline__ void ldm_x4(uint32_t* r, uint32_t addr) {
    asm volatile("ldmatrix.sync.aligned.m8n8.x4.shared.b16 {%0,%1,%2,%3}, [%4];"
                 : "=r"(r[0]), "=r"(r[1]), "=r"(r[2]), "=r"(r[3]) : "r"(addr));
}
__device__ __forceinline__ void mma_bf16(float* c, const uint32_t* a, uint32_t b0, uint32_t b1) {
    asm volatile("mma.sync.aligned.m16n8k16.row.col.f32.bf16.bf16.f32 "
                 "{%0,%1,%2,%3}, {%4,%5,%6,%7}, {%8,%9}, {%0,%1,%2,%3};"
                 : "+f"(c[0]), "+f"(c[1]), "+f"(c[2]), "+f"(c[3])
                 : "r"(a[0]), "r"(a[1]), "r"(a[2]), "r"(a[3]), "r"(b0), "r"(b1));
}

// ---------------- index dtype detection + conversion ------------------------
__global__ void reset_flags_kernel() {
    if (threadIdx.x < 4) g_any32[threadIdx.x] = 0;
}
__global__ void scan_dtype_kernel(const unsigned* __restrict__ p, int nwords, int fi) {
    int i = blockIdx.x * blockDim.x + threadIdx.x;
    if (i >= nwords) return;
    if ((i & 1) && p[i] != 0u) atomicOr(&g_any32[fi], 1);
}
__global__ void convert_idx_kernel(const void* __restrict__ src, int* __restrict__ dst,
                                   int n, int fi) {
    int i = blockIdx.x * blockDim.x + threadIdx.x;
    if (i >= n) return;
    if (g_any32[fi]) dst[i] = ((const int*)src)[i];
    else             dst[i] = (int)((const long long*)src)[i];
}

// ---------------- weight triple-split-pack -----------------------------------
// W3 row layout (per n): chunks of 48 halves: [hi(k0..15) | hi(k0..15) | lo(k0..15)]
__global__ void conv_w_kernel(const float* __restrict__ W, unsigned short* __restrict__ W3,
                              int K, int KP) {
    int idx = blockIdx.x * blockDim.x + threadIdx.x;
    if (idx >= 512 * KP) return;
    int n = idx / KP, k = idx - n * KP;
    float v = (k < K) ? W[(size_t)n * K + k] : 0.f;
    __nv_bfloat16 hb = __float2bfloat16(v);
    float r = v - __bfloat162float(hb);
    __nv_bfloat16 lb = __float2bfloat16(r);
    unsigned short hu = __bfloat16_as_ushort(hb);
    unsigned short lu = __bfloat16_as_ushort(lb);
    size_t base = (size_t)n * KP * 3 + (size_t)(k >> 4) * 48 + (k & 15);
    W3[base]      = hu;
    W3[base + 16] = hu;
    W3[base + 32] = lu;
}

// ---------------- triple-split bf16 tensor GEMM ------------------------------
// C[M,512] = act( A @ W^T (+addmat) (+bias) )
// block 128(M) x 128(N); 8 warps, warp tile 64x32; per 16-k chunk 3 mma k-steps:
//   A segs [hi | lo | hi], B segs [hi | hi | lo] -> hi*hi + lo*hi + hi*lo.
// A modes: 0 = A0[m*lda+k]; 1 = amsg[b2a[m]] - msg[b2revb[m]]; 2 = concat(f_atoms, amsg)
#define PADH 56                    // halves per smem row (48 data + 8 pad) => 112 B
#define ROWB 112
#define BUFB (128 * ROWB)          // 14336 B per matrix per buffer

__global__ __launch_bounds__(256, 2)
void mma_gemm_kernel(const float* __restrict__ A0, int lda, int mode,
                     const float* __restrict__ A1a, const float* __restrict__ A1b,
                     const int* __restrict__ b2a, const int* __restrict__ b2revb,
                     const unsigned short* __restrict__ W3, int K, int KP, int NC,
                     const float* __restrict__ addmat, const float* __restrict__ bias,
                     float* __restrict__ out1, int relu1,
                     float* __restrict__ out2, int M) {
    extern __shared__ char smem[];
    // layout: A buf0 | A buf1 | B buf0 | B buf1
    char* smA = smem;
    char* smB = smem + 2 * BUFB;
    const uint32_t aBase = smem_u32(smA);
    const uint32_t bBase = smem_u32(smB);

    const int tid = threadIdx.x;
    const int wid = tid >> 5, lane = tid & 31;
    const int bm = blockIdx.y * 128;
    const int bn = blockIdx.x * 128;
    const int wm = (wid >> 2) * 64;
    const int wn = (wid & 3) * 32;

    // loader mapping: one row per thread-pair
    const int rL = tid >> 1;       // 0..127
    const int c2 = tid & 1;        // which 8-k half of the 16-k chunk
    const size_t KP3 = (size_t)KP * 3;

    float acc[4][4][4];
    #pragma unroll
    for (int i = 0; i < 4; i++)
        #pragma unroll
        for (int j = 0; j < 4; j++)
            #pragma unroll
            for (int e = 0; e < 4; e++) acc[i][j][e] = 0.f;

    uint4 pah, pal, pb0, pb1, pb2;

    auto load_chunk = [&](int c) {
        int kb = c * 16 + c2 * 8;
        float v[8];
        #pragma unroll
        for (int e = 0; e < 8; e++) v[e] = 0.f;
        int gm = bm + rL;
        if (gm < M) {
            if (mode == 1) {
                int sa = b2a[gm], rb = b2revb[gm];
                const float* pu = A1a + (size_t)sa * HID + kb;
                const float* pw = A1b + (size_t)rb * HID + kb;
                float4 u0 = *(const float4*)(pu);
                float4 u1 = *(const float4*)(pu + 4);
                float4 w0 = *(const float4*)(pw);
                float4 w1 = *(const float4*)(pw + 4);
                v[0] = u0.x - w0.x; v[1] = u0.y - w0.y; v[2] = u0.z - w0.z; v[3] = u0.w - w0.w;
                v[4] = u1.x - w1.x; v[5] = u1.y - w1.y; v[6] = u1.z - w1.z; v[7] = u1.w - w1.w;
            } else if (mode == 0) {
                const float* r = A0 + (size_t)gm * lda;
                #pragma unroll
                for (int e = 0; e < 8; e++)
                    if (kb + e < K) v[e] = r[kb + e];
            } else {
                #pragma unroll
                for (int e = 0; e < 8; e++) {
                    int k = kb + e;
                    if (k < AF) v[e] = A0[(size_t)gm * AF + k];
                    else if (k < K) v[e] = A1a[(size_t)gm * HID + (k - AF)];
                }
            }
        }
        uint32_t h[4], l[4];
        #pragma unroll
        for (int e = 0; e < 4; e++) {
            __nv_bfloat16 h0 = __float2bfloat16(v[2 * e]);
            __nv_bfloat16 h1 = __float2bfloat16(v[2 * e + 1]);
            float r0 = v[2 * e] - __bfloat162float(h0);
            float r1 = v[2 * e + 1] - __bfloat162float(h1);
            __nv_bfloat16 l0 = __float2bfloat16(r0);
            __nv_bfloat16 l1 = __float2bfloat16(r1);
            h[e] = (uint32_t)__bfloat16_as_ushort(h0) | ((uint32_t)__bfloat16_as_ushort(h1) << 16);
            l[e] = (uint32_t)__bfloat16_as_ushort(l0) | ((uint32_t)__bfloat16_as_ushort(l1) << 16);
        }
        pah = make_uint4(h[0], h[1], h[2], h[3]);
        pal = make_uint4(l[0], l[1], l[2], l[3]);
        // B: pre-packed triple layout, contiguous copy of 24 halves per thread
        int gn = bn + rL;                         // GLOBAL weight row (bug fixed)
        const uint4* src = (const uint4*)(W3 + (size_t)gn * KP3 + (size_t)c * 48 + c2 * 24);
        pb0 = src[0]; pb1 = src[1]; pb2 = src[2];
    };
    auto store_chunk = [&](int buf) {
        char* ar = smA + buf * BUFB + rL * ROWB;
        *(uint4*)(ar + c2 * 16)      = pah;   // seg0: hi
        *(uint4*)(ar + 32 + c2 * 16) = pal;   // seg1: lo
        *(uint4*)(ar + 64 + c2 * 16) = pah;   // seg2: hi
        char* br = smB + buf * BUFB + rL * ROWB + c2 * 48;
        *(uint4*)(br)      = pb0;
        *(uint4*)(br + 16) = pb1;
        *(uint4*)(br + 32) = pb2;
    };
    auto compute = [&](int buf) {
        uint32_t a0 = aBase + buf * BUFB;
        uint32_t b0a = bBase + buf * BUFB;
        #pragma unroll
        for (int s = 0; s < 3; s++) {
            uint32_t a[4][4], b[2][4];
            int arow = wm + (lane & 7) + ((lane >> 3) & 1) * 8;
            int acol = s * 16 + (lane >> 4) * 8;
            #pragma unroll
            for (int i = 0; i < 4; i++)
                ldm_x4(a[i], a0 + (arow + i * 16) * ROWB + acol * 2);
            int brow = wn + (lane & 7) + (lane >= 16 ? 8 : 0);
            int bcol = s * 16 + ((lane >> 3) & 1) * 8;
            #pragma unroll
            for (int p = 0; p < 2; p++)
                ldm_x4(b[p], b0a + (brow + p * 16) * ROWB + bcol * 2);
            #pragma unroll
            for (int i = 0; i < 4; i++)
                #pragma unroll
                for (int j = 0; j < 4; j++)
                    mma_bf16(acc[i][j], a[i], b[j >> 1][(j & 1) * 2], b[j >> 1][(j & 1) * 2 + 1]);
        }
    };

    // ---- pipelined main loop ----
    load_chunk(0);
    store_chunk(0);
    __syncthreads();
    for (int c = 0; c < NC; c++) {
        int buf = c & 1;
        if (c + 1 < NC) load_chunk(c + 1);
        compute(buf);
        if (c + 1 < NC) {
            __syncthreads();
            store_chunk(buf ^ 1);
            __syncthreads();
        }
    }

    // ---- epilogue ----
    const int g = lane >> 2, tg = lane & 3;
    #pragma unroll
    for (int i = 0; i < 4; i++) {
        #pragma unroll
        for (int h = 0; h < 2; h++) {
            int gm = bm + wm + i * 16 + g + h * 8;
            if (gm >= M) continue;
            #pragma unroll
            for (int j = 0; j < 4; j++) {
                int gn = bn + wn + j * 8 + tg * 2;
                float v0 = acc[i][j][h * 2 + 0];
                float v1 = acc[i][j][h * 2 + 1];
                if (addmat) {
                    float2 a = *(const float2*)(addmat + (size_t)gm * HID + gn);
                    v0 += a.x; v1 += a.y;
                }
                if (bias) {
                    float2 b = *(const float2*)(bias + gn);
                    v0 += b.x; v1 += b.y;
                }
                float r0 = fmaxf(v0, 0.f), r1 = fmaxf(v1, 0.f);
                float2 o = relu1 ? make_float2(r0, r1) : make_float2(v0, v1);
                *(float2*)(out1 + (size_t)gm * HID + gn) = o;
                if (out2) *(float2*)(out2 + (size_t)gm * HID + gn) = make_float2(r0, r1);
            }
        }
    }
}

// ---------------- gather: a_message[a] = sum_j message[a2b[a][j]] ------------
__global__ void gather_sum_kernel(const float* __restrict__ msg,
                                  float* __restrict__ amsg) {
    int idx = blockIdx.x * blockDim.x + threadIdx.x;
    const int h4 = HID / 4;
    if (idx >= NA * h4) return;
    int a = idx / h4;
    int h = (idx - a * h4) * 4;
    float4 acc = make_float4(0.f, 0.f, 0.f, 0.f);
    #pragma unroll
    for (int j = 0; j < MAXNB; j++) {
        int b = g_a2b[a * MAXNB + j];
        float4 v = *(const float4*)(msg + (size_t)b * HID + h);
        acc.x += v.x; acc.y += v.y; acc.z += v.z; acc.w += v.w;
    }
    *(float4*)(amsg + (size_t)a * HID + h) = acc;
}

// ---------------- pooling ----------------------------------------------------
__global__ void pool_zero_kernel() {
    int i = blockIdx.x * blockDim.x + threadIdx.x;
    if (i < NM * HID) g_sums[i] = 0.f;
    if (i < NM) g_cnt[i] = 0.f;
}
__global__ void pool_sum_kernel(const float* __restrict__ ah) {
    int idx = blockIdx.x * blockDim.x + threadIdx.x;
    const int h4 = HID / 4;
    if (idx >= NA * h4) return;
    int a = idx / h4;
    int h = (idx - a * h4) * 4;
    int m = g_mol[a];
    float4 v = *(const float4*)(ah + (size_t)a * HID + h);
    float* dst = g_sums + (size_t)m * HID + h;
    atomicAdd(dst + 0, v.x);
    atomicAdd(dst + 1, v.y);
    atomicAdd(dst + 2, v.z);
    atomicAdd(dst + 3, v.w);
}
__global__ void pool_count_kernel() {
    int a = blockIdx.x * blockDim.x + threadIdx.x;
    if (a >= NA) return;
    atomicAdd(&g_cnt[g_mol[a]], 1.f);
}
__global__ void finalize_kernel(float* __restrict__ out) {
    int i = blockIdx.x * blockDim.x + threadIdx.x;
    if (i >= NM * HID) return;
    float c = g_cnt[i / HID];
    out[i] = g_sums[i] / fmaxf(c, 1.f);
}

// ---------------- launch -----------------------------------------------------
#define SMEM_GEMM (4 * BUFB)   // 57344 B

extern "C" void kernel_launch(void* const* d_in, const int* in_sizes, int n_in,
                              void* d_out, int out_size) {
    const float* f_atoms = (const float*)d_in[0];
    const float* f_bonds = (const float*)d_in[1];
    const float* W_i     = (const float*)d_in[2];
    const float* W_h     = (const float*)d_in[3];
    const float* W_o     = (const float*)d_in[4];
    const float* b_o     = (const float*)d_in[5];
    const void*  a2b     = d_in[6];
    const void*  b2a     = d_in[7];
    const void*  b2revb  = d_in[8];
    const void*  mol     = d_in[9];
    float* out = (float*)d_out;

    int* d_a2b;    cudaGetSymbolAddress((void**)&d_a2b, g_a2b);
    int* d_b2a;    cudaGetSymbolAddress((void**)&d_b2a, g_b2a);
    int* d_b2revb; cudaGetSymbolAddress((void**)&d_b2revb, g_b2revb);
    int* d_mol;    cudaGetSymbolAddress((void**)&d_mol, g_mol);
    float* d_inp;  cudaGetSymbolAddress((void**)&d_inp, g_inp);
    float* d_msgA; cudaGetSymbolAddress((void**)&d_msgA, g_msgA);
    float* d_msgB; cudaGetSymbolAddress((void**)&d_msgB, g_msgB);
    float* d_amsg; cudaGetSymbolAddress((void**)&d_amsg, g_amsg);
    float* d_ah;   cudaGetSymbolAddress((void**)&d_ah, g_ah);
    unsigned short* d_Wi3; cudaGetSymbolAddress((void**)&d_Wi3, g_Wi3);
    unsigned short* d_Wh3; cudaGetSymbolAddress((void**)&d_Wh3, g_Wh3);
    unsigned short* d_Wo3; cudaGetSymbolAddress((void**)&d_Wo3, g_Wo3);

    static int init_done = 0;
    if (!init_done) {
        cudaFuncSetAttribute(mma_gemm_kernel, cudaFuncAttributeMaxDynamicSharedMemorySize, SMEM_GEMM);
        init_done = 1;
    }

    // 1) canonicalize indices to int32
    reset_flags_kernel<<<1, 32>>>();
    scan_dtype_kernel<<<(NA * MAXNB + 255) / 256, 256>>>((const unsigned*)a2b, NA * MAXNB, 0);
    scan_dtype_kernel<<<(NBOND + 255) / 256, 256>>>((const unsigned*)b2a, NBOND, 1);
    scan_dtype_kernel<<<(NBOND + 255) / 256, 256>>>((const unsigned*)b2revb, NBOND, 2);
    scan_dtype_kernel<<<(NA + 255) / 256, 256>>>((const unsigned*)mol, NA, 3);
    convert_idx_kernel<<<(NA * MAXNB + 255) / 256, 256>>>(a2b, d_a2b, NA * MAXNB, 0);
    convert_idx_kernel<<<(NBOND + 255) / 256, 256>>>(b2a, d_b2a, NBOND, 1);
    convert_idx_kernel<<<(NBOND + 255) / 256, 256>>>(b2revb, d_b2revb, NBOND, 2);
    convert_idx_kernel<<<(NA + 255) / 256, 256>>>(mol, d_mol, NA, 3);

    // 2) triple-split weights
    conv_w_kernel<<<(512 * KP_WI + 255) / 256, 256>>>(W_i, d_Wi3, BF, KP_WI);
    conv_w_kernel<<<(512 * KP_WH + 255) / 256, 256>>>(W_h, d_Wh3, HID, KP_WH);
    conv_w_kernel<<<(512 * KP_WO + 255) / 256, 256>>>(W_o, d_Wo3, AF + HID, KP_WO);

    const int mtiles_b = (NBOND + 127) / 128;   // 938
    const int mtiles_a = (NA + 127) / 128;      // 469

    // 3) inp = f_bonds @ W_i^T ; msg = relu(inp)
    {
        dim3 grid(4, mtiles_b);
        mma_gemm_kernel<<<grid, 256, SMEM_GEMM>>>(
            f_bonds, BF, 0, nullptr, nullptr, nullptr, nullptr,
            d_Wi3, BF, KP_WI, KP_WI / 16,
            nullptr, nullptr, d_inp, 0, d_msgA, NBOND);
    }

    // 4) message passing (bond-update fused into GEMM A-load)
    const int gthreads = 256;
    const int gblocks_a = (NA * (HID / 4) + gthreads - 1) / gthreads;
    float* cur = d_msgA;
    float* alt = d_msgB;
    for (int it = 0; it < 4; it++) {
        gather_sum_kernel<<<gblocks_a, gthreads>>>(cur, d_amsg);
        dim3 grid(4, mtiles_b);
        mma_gemm_kernel<<<grid, 256, SMEM_GEMM>>>(
            nullptr, 0, 1, d_amsg, cur, d_b2a, d_b2revb,
            d_Wh3, HID, KP_WH, KP_WH / 16,
            d_inp, nullptr, alt, 1, nullptr, NBOND);
        float* t = cur; cur = alt; alt = t;
    }

    // 5) final atom gather + output GEMM (concat fused)
    gather_sum_kernel<<<gblocks_a, gthreads>>>(cur, d_amsg);
    {
        dim3 grid(4, mtiles_a);
        mma_gemm_kernel<<<grid, 256, SMEM_GEMM>>>(
            f_atoms, AF, 2, d_amsg, nullptr, nullptr, nullptr,
            d_Wo3, AF + HID, KP_WO, KP_WO / 16,
            nullptr, b_o, d_ah, 1, nullptr, NA);
    }

    // 6) per-molecule mean pooling
    pool_zero_kernel<<<(NM * HID + 255) / 256, 256>>>();
    pool_sum_kernel<<<gblocks_a, gthreads>>>(d_ah);
    pool_count_kernel<<<(NA + 255) / 256, 256>>>();
    finalize_kernel<<<(NM * HID + 255) / 256, 256>>>(out);
}

// round 7
// speedup vs baseline: 2.2768x; 1.2918x over previous
#include <cuda_runtime.h>
#include <cuda_bf16.h>
#include <cstdint>

#define NA 60000
#define NBOND 120000
#define MAXNB 6
#define HID 512
#define AF 133
#define BF 147
#define NM 512

#define KP_WI 160
#define KP_WH 512
#define KP_WO 656

// ---------------- scratch (device globals) -----------------------------------
__device__ float g_inp[(size_t)NBOND * HID];
__device__ float g_msgA[(size_t)NBOND * HID];
__device__ float g_msgB[(size_t)NBOND * HID];
__device__ float g_amsg[(size_t)NA * HID];
__device__ float g_ah[(size_t)NA * HID];
__device__ float g_sums[NM * HID];
__device__ float g_cnt[NM];
__device__ int   g_a2b[NA * MAXNB];
__device__ int   g_b2a[NBOND];
__device__ int   g_b2revb[NBOND];
__device__ int   g_mol[NA];
__device__ int   g_any32[4];
// packed [hi16|lo16] per 16-k chunk
__device__ unsigned short g_Wi2[512 * KP_WI * 2];
__device__ unsigned short g_Wh2[512 * KP_WH * 2];
__device__ unsigned short g_Wo2[512 * KP_WO * 2];
__device__ unsigned short g_pA[(size_t)NBOND * KP_WH * 2];   // max packed-A

// ---------------- helpers -----------------------------------------------------
__device__ __forceinline__ uint32_t smem_u32(const void* p) {
    uint32_t a;
    asm("{ .reg .u64 t; cvta.to.shared.u64 t, %1; cvt.u32.u64 %0, t; }" : "=r"(a) : "l"(p));
    return a;
}
__device__ __forceinline__ void ldm_x4(uint32_t* r, uint32_t addr) {
    asm volatile("ldmatrix.sync.aligned.m8n8.x4.shared.b16 {%0,%1,%2,%3}, [%4];"
                 : "=r"(r[0]), "=r"(r[1]), "=r"(r[2]), "=r"(r[3]) : "r"(addr));
}
__device__ __forceinline__ void mma_bf16(float* c, const uint32_t* a, uint32_t b0, uint32_t b1) {
    asm volatile("mma.sync.aligned.m16n8k16.row.col.f32.bf16.bf16.f32 "
                 "{%0,%1,%2,%3}, {%4,%5,%6,%7}, {%8,%9}, {%0,%1,%2,%3};"
                 : "+f"(c[0]), "+f"(c[1]), "+f"(c[2]), "+f"(c[3])
                 : "r"(a[0]), "r"(a[1]), "r"(a[2]), "r"(a[3]), "r"(b0), "r"(b1));
}
__device__ __forceinline__ void cp16(uint32_t dst, const void* src, int valid) {
    int sz = valid ? 16 : 0;
    asm volatile("cp.async.cg.shared.global [%0], [%1], 16, %2;"
                 :: "r"(dst), "l"(src), "r"(sz) : "memory");
}
__device__ __forceinline__ uint32_t pack2(float a, float b) {
    __nv_bfloat16 ha = __float2bfloat16(a), hb = __float2bfloat16(b);
    return (uint32_t)__bfloat16_as_ushort(ha) | ((uint32_t)__bfloat16_as_ushort(hb) << 16);
}

// ---------------- index dtype detection + conversion -------------------------
__global__ void reset_flags_kernel() {
    if (threadIdx.x < 4) g_any32[threadIdx.x] = 0;
}
__global__ void scan_dtype_kernel(const unsigned* __restrict__ p, int nwords, int fi) {
    int i = blockIdx.x * blockDim.x + threadIdx.x;
    if (i >= nwords) return;
    if ((i & 1) && p[i] != 0u) atomicOr(&g_any32[fi], 1);
}
__global__ void convert_idx_kernel(const void* __restrict__ src, int* __restrict__ dst,
                                   int n, int fi) {
    int i = blockIdx.x * blockDim.x + threadIdx.x;
    if (i >= n) return;
    if (g_any32[fi]) dst[i] = ((const int*)src)[i];
    else             dst[i] = (int)((const long long*)src)[i];
}

// ---------------- weight pack: per n, chunk c: [hi k0..15 | lo k0..15] -------
__global__ void conv_w_kernel(const float* __restrict__ W, unsigned short* __restrict__ Wp,
                              int K, int KP) {
    int idx = blockIdx.x * blockDim.x + threadIdx.x;
    if (idx >= 512 * KP) return;
    int n = idx / KP, k = idx - n * KP;
    float v = (k < K) ? W[(size_t)n * K + k] : 0.f;
    __nv_bfloat16 hb = __float2bfloat16(v);
    float r = v - __bfloat162float(hb);
    __nv_bfloat16 lb = __float2bfloat16(r);
    size_t base = (size_t)n * KP * 2 + (size_t)(k >> 4) * 32 + (k & 15);
    Wp[base]      = __bfloat16_as_ushort(hb);
    Wp[base + 16] = __bfloat16_as_ushort(lb);
}

// ---------------- A pack: modes 0 plain / 1 gather-sub / 2 concat ------------
// out row stride = KP*2 halves; chunk c at byte c*64: [hi 32B | lo 32B]
__global__ void pack_a_kernel(int mode,
                              const float* __restrict__ A0, int lda, int K,
                              const float* __restrict__ A1a, const float* __restrict__ A1b,
                              const int* __restrict__ b2a, const int* __restrict__ b2revb,
                              unsigned short* __restrict__ out, int KP, int M) {
    int t8n = KP >> 3;
    int idx = blockIdx.x * blockDim.x + threadIdx.x;
    if (idx >= M * t8n) return;
    int row = idx / t8n;
    int t8 = idx - row * t8n;
    int kb = t8 * 8;
    float v[8];
    #pragma unroll
    for (int e = 0; e < 8; e++) v[e] = 0.f;
    if (mode == 1) {
        int sa = b2a[row], rb = b2revb[row];
        const float* pu = A1a + (size_t)sa * HID + kb;
        const float* pw = A1b + (size_t)rb * HID + kb;
        float4 u0 = *(const float4*)(pu);
        float4 u1 = *(const float4*)(pu + 4);
        float4 w0 = *(const float4*)(pw);
        float4 w1 = *(const float4*)(pw + 4);
        v[0] = u0.x - w0.x; v[1] = u0.y - w0.y; v[2] = u0.z - w0.z; v[3] = u0.w - w0.w;
        v[4] = u1.x - w1.x; v[5] = u1.y - w1.y; v[6] = u1.z - w1.z; v[7] = u1.w - w1.w;
    } else if (mode == 0) {
        const float* r = A0 + (size_t)row * lda;
        #pragma unroll
        for (int e = 0; e < 8; e++)
            if (kb + e < K) v[e] = r[kb + e];
    } else {
        #pragma unroll
        for (int e = 0; e < 8; e++) {
            int k = kb + e;
            if (k < AF) v[e] = A0[(size_t)row * AF + k];
            else if (k < K) v[e] = A1a[(size_t)row * HID + (k - AF)];
        }
    }
    float lo[8];
    #pragma unroll
    for (int e = 0; e < 8; e++)
        lo[e] = v[e] - __bfloat162float(__float2bfloat16(v[e]));
    uint4 hq = make_uint4(pack2(v[0], v[1]), pack2(v[2], v[3]), pack2(v[4], v[5]), pack2(v[6], v[7]));
    uint4 lq = make_uint4(pack2(lo[0], lo[1]), pack2(lo[2], lo[3]), pack2(lo[4], lo[5]), pack2(lo[6], lo[7]));
    int c = kb >> 4, c2 = (kb >> 3) & 1;
    char* rb_ = (char*)(out + (size_t)row * KP * 2) + c * 64 + c2 * 16;
    *(uint4*)(rb_)      = hq;
    *(uint4*)(rb_ + 32) = lq;
}

// ---------------- packed-A bf16 triple-term tensor GEMM ----------------------
// C[M,512] = act( A @ W^T (+addmat) (+bias) ); block 128Mx128N, 8 warps 64x32.
// smem row = 32 halves [hi|lo] + 8 pad => 80B stride. cp.async double buffer.
#define ROWB 80
#define BUFB (128 * ROWB)

__global__ __launch_bounds__(256, 2)
void mma_gemm_kernel(const unsigned short* __restrict__ pA,
                     const unsigned short* __restrict__ Wp, int KP, int NC,
                     const float* __restrict__ addmat, const float* __restrict__ bias,
                     float* __restrict__ out1, int relu1,
                     float* __restrict__ out2, int M) {
    __shared__ char smA[2][BUFB];
    __shared__ char smB[2][BUFB];
    const uint32_t aBase = smem_u32(&smA[0][0]);
    const uint32_t bBase = smem_u32(&smB[0][0]);

    const int tid = threadIdx.x;
    const int wid = tid >> 5, lane = tid & 31;
    const int bm = blockIdx.y * 128;
    const int bn = blockIdx.x * 128;
    const int wm = (wid >> 2) * 64;
    const int wn = (wid & 3) * 32;

    const int rL = tid >> 1;       // 0..127
    const int c2 = tid & 1;        // which 32B half-chunk
    const int gmL = bm + rL;
    const int okA = gmL < M;
    const char* gA = (const char*)(pA + (size_t)gmL * KP * 2) + c2 * 32;
    const char* gB = (const char*)(Wp + (size_t)(bn + rL) * KP * 2) + c2 * 32;
    const uint32_t sA = aBase + rL * ROWB + c2 * 32;
    const uint32_t sB = bBase + rL * ROWB + c2 * 32;

    float acc[4][4][4];
    #pragma unroll
    for (int i = 0; i < 4; i++)
        #pragma unroll
        for (int j = 0; j < 4; j++)
            #pragma unroll
            for (int e = 0; e < 4; e++) acc[i][j][e] = 0.f;

    auto prefetch = [&](int c, int buf) {
        const char* a = gA + (size_t)c * 64;
        const char* b = gB + (size_t)c * 64;
        cp16(sA + buf * BUFB, a, okA);
        cp16(sA + buf * BUFB + 16, a + 16, okA);
        cp16(sB + buf * BUFB, b, 1);
        cp16(sB + buf * BUFB + 16, b + 16, 1);
        asm volatile("cp.async.commit_group;" ::: "memory");
    };

    // frag addresses (constant across chunks except buffer offset)
    const uint32_t aAddr = aBase + (wm + (lane & 15)) * ROWB + (lane >> 4) * 16;
    const uint32_t bAddr = bBase + (wn + (lane & 7) + (lane >= 16 ? 8 : 0)) * ROWB
                                 + ((lane >> 3) & 1) * 16;

    prefetch(0, 0);
    for (int c = 0; c < NC; c++) {
        int buf = c & 1;
        if (c + 1 < NC) {
            prefetch(c + 1, buf ^ 1);
            asm volatile("cp.async.wait_group 1;" ::: "memory");
        } else {
            asm volatile("cp.async.wait_group 0;" ::: "memory");
        }
        __syncthreads();

        uint32_t aH[4][4], aL[4][4], bH[2][4], bL[2][4];
        #pragma unroll
        for (int i = 0; i < 4; i++) {
            ldm_x4(aH[i], aAddr + buf * BUFB + i * 16 * ROWB);
            ldm_x4(aL[i], aAddr + buf * BUFB + i * 16 * ROWB + 32);
        }
        #pragma unroll
        for (int p = 0; p < 2; p++) {
            ldm_x4(bH[p], bAddr + buf * BUFB + p * 16 * ROWB);
            ldm_x4(bL[p], bAddr + buf * BUFB + p * 16 * ROWB + 32);
        }
        #pragma unroll
        for (int i = 0; i < 4; i++)
            #pragma unroll
            for (int j = 0; j < 4; j++) {
                mma_bf16(acc[i][j], aH[i], bH[j >> 1][(j & 1) * 2], bH[j >> 1][(j & 1) * 2 + 1]);
                mma_bf16(acc[i][j], aL[i], bH[j >> 1][(j & 1) * 2], bH[j >> 1][(j & 1) * 2 + 1]);
                mma_bf16(acc[i][j], aH[i], bL[j >> 1][(j & 1) * 2], bL[j >> 1][(j & 1) * 2 + 1]);
            }
        __syncthreads();
    }

    // ---- epilogue ----
    const int g = lane >> 2, tg = lane & 3;
    #pragma unroll
    for (int i = 0; i < 4; i++) {
        #pragma unroll
        for (int h = 0; h < 2; h++) {
            int gm = bm + wm + i * 16 + g + h * 8;
            if (gm >= M) continue;
            #pragma unroll
            for (int j = 0; j < 4; j++) {
                int gn = bn + wn + j * 8 + tg * 2;
                float v0 = acc[i][j][h * 2 + 0];
                float v1 = acc[i][j][h * 2 + 1];
                if (addmat) {
                    float2 a = *(const float2*)(addmat + (size_t)gm * HID + gn);
                    v0 += a.x; v1 += a.y;
                }
                if (bias) {
                    float2 b = *(const float2*)(bias + gn);
                    v0 += b.x; v1 += b.y;
                }
                float r0 = fmaxf(v0, 0.f), r1 = fmaxf(v1, 0.f);
                float2 o = relu1 ? make_float2(r0, r1) : make_float2(v0, v1);
                *(float2*)(out1 + (size_t)gm * HID + gn) = o;
                if (out2) *(float2*)(out2 + (size_t)gm * HID + gn) = make_float2(r0, r1);
            }
        }
    }
}

// ---------------- gather: a_message[a] = sum_j message[a2b[a][j]] ------------
__global__ void gather_sum_kernel(const float* __restrict__ msg,
                                  float* __restrict__ amsg) {
    int idx = blockIdx.x * blockDim.x + threadIdx.x;
    const int h4 = HID / 4;
    if (idx >= NA * h4) return;
    int a = idx / h4;
    int h = (idx - a * h4) * 4;
    float4 acc = make_float4(0.f, 0.f, 0.f, 0.f);
    #pragma unroll
    for (int j = 0; j < MAXNB; j++) {
        int b = g_a2b[a * MAXNB + j];
        float4 v = *(const float4*)(msg + (size_t)b * HID + h);
        acc.x += v.x; acc.y += v.y; acc.z += v.z; acc.w += v.w;
    }
    *(float4*)(amsg + (size_t)a * HID + h) = acc;
}

// ---------------- pooling -----------------------------------------------------
__global__ void pool_zero_kernel() {
    int i = blockIdx.x * blockDim.x + threadIdx.x;
    if (i < NM * HID) g_sums[i] = 0.f;
    if (i < NM) g_cnt[i] = 0.f;
}
__global__ void pool_sum_kernel(const float* __restrict__ ah) {
    int idx = blockIdx.x * blockDim.x + threadIdx.x;
    const int h4 = HID / 4;
    if (idx >= NA * h4) return;
    int a = idx / h4;
    int h = (idx - a * h4) * 4;
    int m = g_mol[a];
    float4 v = *(const float4*)(ah + (size_t)a * HID + h);
    float* dst = g_sums + (size_t)m * HID + h;
    atomicAdd(dst + 0, v.x);
    atomicAdd(dst + 1, v.y);
    atomicAdd(dst + 2, v.z);
    atomicAdd(dst + 3, v.w);
}
__global__ void pool_count_kernel() {
    int a = blockIdx.x * blockDim.x + threadIdx.x;
    if (a >= NA) return;
    atomicAdd(&g_cnt[g_mol[a]], 1.f);
}
__global__ void finalize_kernel(float* __restrict__ out) {
    int i = blockIdx.x * blockDim.x + threadIdx.x;
    if (i >= NM * HID) return;
    float c = g_cnt[i / HID];
    out[i] = g_sums[i] / fmaxf(c, 1.f);
}

// ---------------- launch ------------------------------------------------------
extern "C" void kernel_launch(void* const* d_in, const int* in_sizes, int n_in,
                              void* d_out, int out_size) {
    const float* f_atoms = (const float*)d_in[0];
    const float* f_bonds = (const float*)d_in[1];
    const float* W_i     = (const float*)d_in[2];
    const float* W_h     = (const float*)d_in[3];
    const float* W_o     = (const float*)d_in[4];
    const float* b_o     = (const float*)d_in[5];
    const void*  a2b     = d_in[6];
    const void*  b2a     = d_in[7];
    const void*  b2revb  = d_in[8];
    const void*  mol     = d_in[9];
    float* out = (float*)d_out;

    int* d_a2b;    cudaGetSymbolAddress((void**)&d_a2b, g_a2b);
    int* d_b2a;    cudaGetSymbolAddress((void**)&d_b2a, g_b2a);
    int* d_b2revb; cudaGetSymbolAddress((void**)&d_b2revb, g_b2revb);
    int* d_mol;    cudaGetSymbolAddress((void**)&d_mol, g_mol);
    float* d_inp;  cudaGetSymbolAddress((void**)&d_inp, g_inp);
    float* d_msgA; cudaGetSymbolAddress((void**)&d_msgA, g_msgA);
    float* d_msgB; cudaGetSymbolAddress((void**)&d_msgB, g_msgB);
    float* d_amsg; cudaGetSymbolAddress((void**)&d_amsg, g_amsg);
    float* d_ah;   cudaGetSymbolAddress((void**)&d_ah, g_ah);
    unsigned short* d_Wi2; cudaGetSymbolAddress((void**)&d_Wi2, g_Wi2);
    unsigned short* d_Wh2; cudaGetSymbolAddress((void**)&d_Wh2, g_Wh2);
    unsigned short* d_Wo2; cudaGetSymbolAddress((void**)&d_Wo2, g_Wo2);
    unsigned short* d_pA;  cudaGetSymbolAddress((void**)&d_pA, g_pA);

    // 1) canonicalize indices
    reset_flags_kernel<<<1, 32>>>();
    scan_dtype_kernel<<<(NA * MAXNB + 255) / 256, 256>>>((const unsigned*)a2b, NA * MAXNB, 0);
    scan_dtype_kernel<<<(NBOND + 255) / 256, 256>>>((const unsigned*)b2a, NBOND, 1);
    scan_dtype_kernel<<<(NBOND + 255) / 256, 256>>>((const unsigned*)b2revb, NBOND, 2);
    scan_dtype_kernel<<<(NA + 255) / 256, 256>>>((const unsigned*)mol, NA, 3);
    convert_idx_kernel<<<(NA * MAXNB + 255) / 256, 256>>>(a2b, d_a2b, NA * MAXNB, 0);
    convert_idx_kernel<<<(NBOND + 255) / 256, 256>>>(b2a, d_b2a, NBOND, 1);
    convert_idx_kernel<<<(NBOND + 255) / 256, 256>>>(b2revb, d_b2revb, NBOND, 2);
    convert_idx_kernel<<<(NA + 255) / 256, 256>>>(mol, d_mol, NA, 3);

    // 2) pack weights
    conv_w_kernel<<<(512 * KP_WI + 255) / 256, 256>>>(W_i, d_Wi2, BF, KP_WI);
    conv_w_kernel<<<(512 * KP_WH + 255) / 256, 256>>>(W_h, d_Wh2, HID, KP_WH);
    conv_w_kernel<<<(512 * KP_WO + 255) / 256, 256>>>(W_o, d_Wo2, AF + HID, KP_WO);

    const int mtiles_b = (NBOND + 127) / 128;
    const int mtiles_a = (NA + 127) / 128;
    const int gthreads = 256;
    const int gblocks_a = (NA * (HID / 4) + gthreads - 1) / gthreads;

    // 3) inp = f_bonds @ W_i^T ; msg = relu(inp)
    pack_a_kernel<<<(NBOND * (KP_WI / 8) + 255) / 256, 256>>>(
        0, f_bonds, BF, BF, nullptr, nullptr, nullptr, nullptr, d_pA, KP_WI, NBOND);
    mma_gemm_kernel<<<dim3(4, mtiles_b), 256>>>(
        d_pA, d_Wi2, KP_WI, KP_WI / 16, nullptr, nullptr, d_inp, 0, d_msgA, NBOND);

    // 4) message passing
    float* cur = d_msgA;
    float* alt = d_msgB;
    for (int it = 0; it < 4; it++) {
        gather_sum_kernel<<<gblocks_a, gthreads>>>(cur, d_amsg);
        pack_a_kernel<<<(NBOND * (KP_WH / 8) + 255) / 256, 256>>>(
            1, nullptr, 0, HID, d_amsg, cur, d_b2a, d_b2revb, d_pA, KP_WH, NBOND);
        mma_gemm_kernel<<<dim3(4, mtiles_b), 256>>>(
            d_pA, d_Wh2, KP_WH, KP_WH / 16, d_inp, nullptr, alt, 1, nullptr, NBOND);
        float* t = cur; cur = alt; alt = t;
    }

    // 5) final gather + output GEMM
    gather_sum_kernel<<<gblocks_a, gthreads>>>(cur, d_amsg);
    pack_a_kernel<<<(NA * (KP_WO / 8) + 255) / 256, 256>>>(
        2, f_atoms, AF, AF + HID, d_amsg, nullptr, nullptr, nullptr, d_pA, KP_WO, NA);
    mma_gemm_kernel<<<dim3(4, mtiles_a), 256>>>(
        d_pA, d_Wo2, KP_WO, KP_WO / 16, nullptr, b_o, d_ah, 1, nullptr, NA);

    // 6) per-molecule mean pooling
    pool_zero_kernel<<<(NM * HID + 255) / 256, 256>>>();
    pool_sum_kernel<<<gblocks_a, gthreads>>>(d_ah);
    pool_count_kernel<<<(NA + 255) / 256, 256>>>();
    finalize_kernel<<<(NM * HID + 255) / 256, 256>>>(out);
}

// round 8
// speedup vs baseline: 2.3115x; 1.0152x over previous
#include <cuda_runtime.h>
#include <cuda_bf16.h>
#include <cstdint>

#define NA 60000
#define NBOND 120000
#define MAXNB 6
#define HID 512
#define AF 133
#define BF 147
#define NM 512

#define KP_WI 160
#define KP_WH 512
#define KP_WO 656

// ---------------- scratch (device globals) -----------------------------------
__device__ float g_inp[(size_t)NBOND * HID];
__device__ float g_msgA[(size_t)NBOND * HID];
__device__ float g_msgB[(size_t)NBOND * HID];
__device__ float g_amsg[(size_t)NA * HID];
__device__ float g_ah[(size_t)NA * HID];
__device__ float g_sums[NM * HID];
__device__ float g_cnt[NM];
__device__ int   g_a2b[NA * MAXNB];
__device__ int   g_b2a[NBOND];
__device__ int   g_b2revb[NBOND];
__device__ int   g_mol[NA];
__device__ int   g_any32[4];
// packed [hi16|lo16] per 16-k chunk
__device__ unsigned short g_Wi2[512 * KP_WI * 2];
__device__ unsigned short g_Wh2[512 * KP_WH * 2];
__device__ unsigned short g_Wo2[512 * KP_WO * 2];
__device__ unsigned short g_pA[(size_t)NA * KP_WO * 2];   // packed-A (W_i / W_o paths)

// ---------------- helpers -----------------------------------------------------
__device__ __forceinline__ uint32_t smem_u32(const void* p) {
    uint32_t a;
    asm("{ .reg .u64 t; cvta.to.shared.u64 t, %1; cvt.u32.u64 %0, t; }" : "=r"(a) : "l"(p));
    return a;
}
__device__ __forceinline__ void ldm_x4(uint32_t* r, uint32_t addr) {
    asm volatile("ldmatrix.sync.aligned.m8n8.x4.shared.b16 {%0,%1,%2,%3}, [%4];"
                 : "=r"(r[0]), "=r"(r[1]), "=r"(r[2]), "=r"(r[3]) : "r"(addr));
}
__device__ __forceinline__ void mma_bf16(float* c, const uint32_t* a, uint32_t b0, uint32_t b1) {
    asm volatile("mma.sync.aligned.m16n8k16.row.col.f32.bf16.bf16.f32 "
                 "{%0,%1,%2,%3}, {%4,%5,%6,%7}, {%8,%9}, {%0,%1,%2,%3};"
                 : "+f"(c[0]), "+f"(c[1]), "+f"(c[2]), "+f"(c[3])
                 : "r"(a[0]), "r"(a[1]), "r"(a[2]), "r"(a[3]), "r"(b0), "r"(b1));
}
__device__ __forceinline__ void cp16(uint32_t dst, const void* src, int valid) {
    int sz = valid ? 16 : 0;
    asm volatile("cp.async.cg.shared.global [%0], [%1], 16, %2;"
                 :: "r"(dst), "l"(src), "r"(sz) : "memory");
}
__device__ __forceinline__ uint32_t pack2(float a, float b) {
    __nv_bfloat16 ha = __float2bfloat16(a), hb = __float2bfloat16(b);
    return (uint32_t)__bfloat16_as_ushort(ha) | ((uint32_t)__bfloat16_as_ushort(hb) << 16);
}

// ---------------- index dtype detection + conversion -------------------------
__global__ void reset_flags_kernel() {
    if (threadIdx.x < 4) g_any32[threadIdx.x] = 0;
}
__global__ void scan_dtype_kernel(const unsigned* __restrict__ p, int nwords, int fi) {
    int i = blockIdx.x * blockDim.x + threadIdx.x;
    if (i >= nwords) return;
    if ((i & 1) && p[i] != 0u) atomicOr(&g_any32[fi], 1);
}
__global__ void convert_idx_kernel(const void* __restrict__ src, int* __restrict__ dst,
                                   int n, int fi) {
    int i = blockIdx.x * blockDim.x + threadIdx.x;
    if (i >= n) return;
    if (g_any32[fi]) dst[i] = ((const int*)src)[i];
    else             dst[i] = (int)((const long long*)src)[i];
}

// ---------------- weight pack: per n, chunk c: [hi k0..15 | lo k0..15] -------
__global__ void conv_w_kernel(const float* __restrict__ W, unsigned short* __restrict__ Wp,
                              int K, int KP) {
    int idx = blockIdx.x * blockDim.x + threadIdx.x;
    if (idx >= 512 * KP) return;
    int n = idx / KP, k = idx - n * KP;
    float v = (k < K) ? W[(size_t)n * K + k] : 0.f;
    __nv_bfloat16 hb = __float2bfloat16(v);
    float r = v - __bfloat162float(hb);
    __nv_bfloat16 lb = __float2bfloat16(r);
    size_t base = (size_t)n * KP * 2 + (size_t)(k >> 4) * 32 + (k & 15);
    Wp[base]      = __bfloat16_as_ushort(hb);
    Wp[base + 16] = __bfloat16_as_ushort(lb);
}

// ---------------- A pack: modes 0 plain / 2 concat ---------------------------
__global__ void pack_a_kernel(int mode,
                              const float* __restrict__ A0, int lda, int K,
                              const float* __restrict__ A1a,
                              unsigned short* __restrict__ out, int KP, int M) {
    int t8n = KP >> 3;
    int idx = blockIdx.x * blockDim.x + threadIdx.x;
    if (idx >= M * t8n) return;
    int row = idx / t8n;
    int t8 = idx - row * t8n;
    int kb = t8 * 8;
    float v[8];
    #pragma unroll
    for (int e = 0; e < 8; e++) v[e] = 0.f;
    if (mode == 0) {
        const float* r = A0 + (size_t)row * lda;
        #pragma unroll
        for (int e = 0; e < 8; e++)
            if (kb + e < K) v[e] = r[kb + e];
    } else {
        #pragma unroll
        for (int e = 0; e < 8; e++) {
            int k = kb + e;
            if (k < AF) v[e] = A0[(size_t)row * AF + k];
            else if (k < K) v[e] = A1a[(size_t)row * HID + (k - AF)];
        }
    }
    float lo[8];
    #pragma unroll
    for (int e = 0; e < 8; e++)
        lo[e] = v[e] - __bfloat162float(__float2bfloat16(v[e]));
    uint4 hq = make_uint4(pack2(v[0], v[1]), pack2(v[2], v[3]), pack2(v[4], v[5]), pack2(v[6], v[7]));
    uint4 lq = make_uint4(pack2(lo[0], lo[1]), pack2(lo[2], lo[3]), pack2(lo[4], lo[5]), pack2(lo[6], lo[7]));
    int c = kb >> 4, c2 = (kb >> 3) & 1;
    char* rb_ = (char*)(out + (size_t)row * KP * 2) + c * 64 + c2 * 16;
    *(uint4*)(rb_)      = hq;
    *(uint4*)(rb_ + 32) = lq;
}

// ---------------- shared GEMM geometry ---------------------------------------
#define ROWB 80
#define BUFB (128 * ROWB)

// ---------------- packed-A GEMM (W_i / W_o paths), as R7 ---------------------
__global__ __launch_bounds__(256, 2)
void mma_gemm_kernel(const unsigned short* __restrict__ pA,
                     const unsigned short* __restrict__ Wp, int KP, int NC,
                     const float* __restrict__ addmat, const float* __restrict__ bias,
                     float* __restrict__ out1, int relu1,
                     float* __restrict__ out2, int M) {
    __shared__ char smA[2][BUFB];
    __shared__ char smB[2][BUFB];
    const uint32_t aBase = smem_u32(&smA[0][0]);
    const uint32_t bBase = smem_u32(&smB[0][0]);

    const int tid = threadIdx.x;
    const int wid = tid >> 5, lane = tid & 31;
    const int bm = blockIdx.y * 128;
    const int bn = blockIdx.x * 128;
    const int wm = (wid >> 2) * 64;
    const int wn = (wid & 3) * 32;

    const int rL = tid >> 1;
    const int c2 = tid & 1;
    const int gmL = bm + rL;
    const int okA = gmL < M;
    const char* gA = (const char*)(pA + (size_t)gmL * KP * 2) + c2 * 32;
    const char* gB = (const char*)(Wp + (size_t)(bn + rL) * KP * 2) + c2 * 32;
    const uint32_t sA = aBase + rL * ROWB + c2 * 32;
    const uint32_t sB = bBase + rL * ROWB + c2 * 32;

    float acc[4][4][4];
    #pragma unroll
    for (int i = 0; i < 4; i++)
        #pragma unroll
        for (int j = 0; j < 4; j++)
            #pragma unroll
            for (int e = 0; e < 4; e++) acc[i][j][e] = 0.f;

    auto prefetch = [&](int c, int buf) {
        const char* a = gA + (size_t)c * 64;
        const char* b = gB + (size_t)c * 64;
        cp16(sA + buf * BUFB, a, okA);
        cp16(sA + buf * BUFB + 16, a + 16, okA);
        cp16(sB + buf * BUFB, b, 1);
        cp16(sB + buf * BUFB + 16, b + 16, 1);
        asm volatile("cp.async.commit_group;" ::: "memory");
    };

    const uint32_t aAddr = aBase + (wm + (lane & 15)) * ROWB + (lane >> 4) * 16;
    const uint32_t bAddr = bBase + (wn + (lane & 7) + (lane >= 16 ? 8 : 0)) * ROWB
                                 + ((lane >> 3) & 1) * 16;

    prefetch(0, 0);
    for (int c = 0; c < NC; c++) {
        int buf = c & 1;
        if (c + 1 < NC) {
            prefetch(c + 1, buf ^ 1);
            asm volatile("cp.async.wait_group 1;" ::: "memory");
        } else {
            asm volatile("cp.async.wait_group 0;" ::: "memory");
        }
        __syncthreads();

        uint32_t aH[4][4], aL[4][4], bH[2][4], bL[2][4];
        #pragma unroll
        for (int i = 0; i < 4; i++) {
            ldm_x4(aH[i], aAddr + buf * BUFB + i * 16 * ROWB);
            ldm_x4(aL[i], aAddr + buf * BUFB + i * 16 * ROWB + 32);
        }
        #pragma unroll
        for (int p = 0; p < 2; p++) {
            ldm_x4(bH[p], bAddr + buf * BUFB + p * 16 * ROWB);
            ldm_x4(bL[p], bAddr + buf * BUFB + p * 16 * ROWB + 32);
        }
        #pragma unroll
        for (int i = 0; i < 4; i++)
            #pragma unroll
            for (int j = 0; j < 4; j++) {
                mma_bf16(acc[i][j], aH[i], bH[j >> 1][(j & 1) * 2], bH[j >> 1][(j & 1) * 2 + 1]);
                mma_bf16(acc[i][j], aL[i], bH[j >> 1][(j & 1) * 2], bH[j >> 1][(j & 1) * 2 + 1]);
                mma_bf16(acc[i][j], aH[i], bL[j >> 1][(j & 1) * 2], bL[j >> 1][(j & 1) * 2 + 1]);
            }
        __syncthreads();
    }

    const int g = lane >> 2, tg = lane & 3;
    #pragma unroll
    for (int i = 0; i < 4; i++) {
        #pragma unroll
        for (int h = 0; h < 2; h++) {
            int gm = bm + wm + i * 16 + g + h * 8;
            if (gm >= M) continue;
            #pragma unroll
            for (int j = 0; j < 4; j++) {
                int gn = bn + wn + j * 8 + tg * 2;
                float v0 = acc[i][j][h * 2 + 0];
                float v1 = acc[i][j][h * 2 + 1];
                if (addmat) {
                    float2 a = *(const float2*)(addmat + (size_t)gm * HID + gn);
                    v0 += a.x; v1 += a.y;
                }
                if (bias) {
                    float2 b = *(const float2*)(bias + gn);
                    v0 += b.x; v1 += b.y;
                }
                float r0 = fmaxf(v0, 0.f), r1 = fmaxf(v1, 0.f);
                float2 o = relu1 ? make_float2(r0, r1) : make_float2(v0, v1);
                *(float2*)(out1 + (size_t)gm * HID + gn) = o;
                if (out2) *(float2*)(out2 + (size_t)gm * HID + gn) = make_float2(r0, r1);
            }
        }
    }
}

// ---------------- fused W_h GEMM: A = amsg[b2a[m]] - msg[b2revb[m]] ----------
// msg_new = relu(inp + A @ W_h^T). A split to bf16 hi/lo in-loader; B cp.async.
__global__ __launch_bounds__(256, 2)
void mma_gemm_fused_kernel(const float* __restrict__ amsg,
                           const float* __restrict__ msg,
                           const int* __restrict__ b2a,
                           const int* __restrict__ b2revb,
                           const unsigned short* __restrict__ Wp,
                           const float* __restrict__ inp,
                           float* __restrict__ out1) {
    const int NC = KP_WH / 16;   // 32 chunks
    __shared__ char smA[2][BUFB];
    __shared__ char smB[2][BUFB];
    const uint32_t aBase = smem_u32(&smA[0][0]);
    const uint32_t bBase = smem_u32(&smB[0][0]);

    const int tid = threadIdx.x;
    const int wid = tid >> 5, lane = tid & 31;
    const int bm = blockIdx.y * 128;
    const int bn = blockIdx.x * 128;
    const int wm = (wid >> 2) * 64;
    const int wn = (wid & 3) * 32;

    const int rL = tid >> 1;      // row 0..127
    const int c2 = tid & 1;       // 8-float half of the 16-k chunk
    const int gmL = bm + rL;
    const int okA = gmL < NBOND;
    const int sa = okA ? b2a[gmL] : 0;
    const int rb = okA ? b2revb[gmL] : 0;
    const char* gU = (const char*)(amsg + (size_t)sa * HID) + c2 * 32;
    const char* gW = (const char*)(msg + (size_t)rb * HID) + c2 * 32;
    const char* gB = (const char*)(Wp + (size_t)(bn + rL) * KP_WH * 2) + c2 * 32;
    const uint32_t sB = bBase + rL * ROWB + c2 * 32;

    float acc[4][4][4];
    #pragma unroll
    for (int i = 0; i < 4; i++)
        #pragma unroll
        for (int j = 0; j < 4; j++)
            #pragma unroll
            for (int e = 0; e < 4; e++) acc[i][j][e] = 0.f;

    uint4 hq, lq;   // staged packed A for next store

    auto loadA = [&](int c) {
        float v[8];
        if (okA) {
            const char* u = gU + (size_t)c * 64;
            const char* w = gW + (size_t)c * 64;
            float4 u0 = *(const float4*)(u);
            float4 u1 = *(const float4*)(u + 16);
            float4 w0 = *(const float4*)(w);
            float4 w1 = *(const float4*)(w + 16);
            v[0] = u0.x - w0.x; v[1] = u0.y - w0.y; v[2] = u0.z - w0.z; v[3] = u0.w - w0.w;
            v[4] = u1.x - w1.x; v[5] = u1.y - w1.y; v[6] = u1.z - w1.z; v[7] = u1.w - w1.w;
        } else {
            #pragma unroll
            for (int e = 0; e < 8; e++) v[e] = 0.f;
        }
        float lo[8];
        #pragma unroll
        for (int e = 0; e < 8; e++)
            lo[e] = v[e] - __bfloat162float(__float2bfloat16(v[e]));
        hq = make_uint4(pack2(v[0], v[1]), pack2(v[2], v[3]), pack2(v[4], v[5]), pack2(v[6], v[7]));
        lq = make_uint4(pack2(lo[0], lo[1]), pack2(lo[2], lo[3]), pack2(lo[4], lo[5]), pack2(lo[6], lo[7]));
    };
    auto storeA = [&](int buf) {
        char* ar = smA[buf] + rL * ROWB;
        *(uint4*)(ar + c2 * 16)      = hq;
        *(uint4*)(ar + 32 + c2 * 16) = lq;
    };
    auto prefetchB = [&](int c, int buf) {
        const char* b = gB + (size_t)c * 64;
        cp16(sB + buf * BUFB, b, 1);
        cp16(sB + buf * BUFB + 16, b + 16, 1);
        asm volatile("cp.async.commit_group;" ::: "memory");
    };

    const uint32_t aAddr = aBase + (wm + (lane & 15)) * ROWB + (lane >> 4) * 16;
    const uint32_t bAddr = bBase + (wn + (lane & 7) + (lane >= 16 ? 8 : 0)) * ROWB
                                 + ((lane >> 3) & 1) * 16;

    loadA(0);
    prefetchB(0, 0);
    storeA(0);
    for (int c = 0; c < NC; c++) {
        int buf = c & 1;
        if (c + 1 < NC) {
            loadA(c + 1);                 // LDGs issued early; used after compute
            prefetchB(c + 1, buf ^ 1);
            asm volatile("cp.async.wait_group 1;" ::: "memory");
        } else {
            asm volatile("cp.async.wait_group 0;" ::: "memory");
        }
        __syncthreads();

        // compute on buf; aH fragment registers reused for aL (reg pressure)
        uint32_t af[4][4], bH[2][4], bL[2][4];
        #pragma unroll
        for (int p = 0; p < 2; p++) {
            ldm_x4(bH[p], bAddr + buf * BUFB + p * 16 * ROWB);
            ldm_x4(bL[p], bAddr + buf * BUFB + p * 16 * ROWB + 32);
        }
        #pragma unroll
        for (int i = 0; i < 4; i++)
            ldm_x4(af[i], aAddr + buf * BUFB + i * 16 * ROWB);        // aH
        #pragma unroll
        for (int i = 0; i < 4; i++)
            #pragma unroll
            for (int j = 0; j < 4; j++) {
                mma_bf16(acc[i][j], af[i], bH[j >> 1][(j & 1) * 2], bH[j >> 1][(j & 1) * 2 + 1]);
                mma_bf16(acc[i][j], af[i], bL[j >> 1][(j & 1) * 2], bL[j >> 1][(j & 1) * 2 + 1]);
            }
        #pragma unroll
        for (int i = 0; i < 4; i++)
            ldm_x4(af[i], aAddr + buf * BUFB + i * 16 * ROWB + 32);   // aL
        #pragma unroll
        for (int i = 0; i < 4; i++)
            #pragma unroll
            for (int j = 0; j < 4; j++)
                mma_bf16(acc[i][j], af[i], bH[j >> 1][(j & 1) * 2], bH[j >> 1][(j & 1) * 2 + 1]);

        __syncthreads();
        if (c + 1 < NC) storeA(buf ^ 1);
    }

    // epilogue: relu(inp + acc) -> out1
    const int g = lane >> 2, tg = lane & 3;
    #pragma unroll
    for (int i = 0; i < 4; i++) {
        #pragma unroll
        for (int h = 0; h < 2; h++) {
            int gm = bm + wm + i * 16 + g + h * 8;
            if (gm >= NBOND) continue;
            #pragma unroll
            for (int j = 0; j < 4; j++) {
                int gn = bn + wn + j * 8 + tg * 2;
                float2 a = *(const float2*)(inp + (size_t)gm * HID + gn);
                float v0 = acc[i][j][h * 2 + 0] + a.x;
                float v1 = acc[i][j][h * 2 + 1] + a.y;
                *(float2*)(out1 + (size_t)gm * HID + gn) =
                    make_float2(fmaxf(v0, 0.f), fmaxf(v1, 0.f));
            }
        }
    }
}

// ---------------- gather: a_message[a] = sum_j message[a2b[a][j]] ------------
__global__ void gather_sum_kernel(const float* __restrict__ msg,
                                  float* __restrict__ amsg) {
    int idx = blockIdx.x * blockDim.x + threadIdx.x;
    const int h4 = HID / 4;
    if (idx >= NA * h4) return;
    int a = idx / h4;
    int h = (idx - a * h4) * 4;
    float4 acc = make_float4(0.f, 0.f, 0.f, 0.f);
    #pragma unroll
    for (int j = 0; j < MAXNB; j++) {
        int b = g_a2b[a * MAXNB + j];
        float4 v = *(const float4*)(msg + (size_t)b * HID + h);
        acc.x += v.x; acc.y += v.y; acc.z += v.z; acc.w += v.w;
    }
    *(float4*)(amsg + (size_t)a * HID + h) = acc;
}

// ---------------- pooling -----------------------------------------------------
__global__ void pool_zero_kernel() {
    int i = blockIdx.x * blockDim.x + threadIdx.x;
    if (i < NM * HID) g_sums[i] = 0.f;
    if (i < NM) g_cnt[i] = 0.f;
}
__global__ void pool_sum_kernel(const float* __restrict__ ah) {
    int idx = blockIdx.x * blockDim.x + threadIdx.x;
    const int h4 = HID / 4;
    if (idx >= NA * h4) return;
    int a = idx / h4;
    int h = (idx - a * h4) * 4;
    int m = g_mol[a];
    float4 v = *(const float4*)(ah + (size_t)a * HID + h);
    float* dst = g_sums + (size_t)m * HID + h;
    atomicAdd(dst + 0, v.x);
    atomicAdd(dst + 1, v.y);
    atomicAdd(dst + 2, v.z);
    atomicAdd(dst + 3, v.w);
}
__global__ void pool_count_kernel() {
    int a = blockIdx.x * blockDim.x + threadIdx.x;
    if (a >= NA) return;
    atomicAdd(&g_cnt[g_mol[a]], 1.f);
}
__global__ void finalize_kernel(float* __restrict__ out) {
    int i = blockIdx.x * blockDim.x + threadIdx.x;
    if (i >= NM * HID) return;
    float c = g_cnt[i / HID];
    out[i] = g_sums[i] / fmaxf(c, 1.f);
}

// ---------------- launch ------------------------------------------------------
extern "C" void kernel_launch(void* const* d_in, const int* in_sizes, int n_in,
                              void* d_out, int out_size) {
    const float* f_atoms = (const float*)d_in[0];
    const float* f_bonds = (const float*)d_in[1];
    const float* W_i     = (const float*)d_in[2];
    const float* W_h     = (const float*)d_in[3];
    const float* W_o     = (const float*)d_in[4];
    const float* b_o     = (const float*)d_in[5];
    const void*  a2b     = d_in[6];
    const void*  b2a     = d_in[7];
    const void*  b2revb  = d_in[8];
    const void*  mol     = d_in[9];
    float* out = (float*)d_out;

    int* d_a2b;    cudaGetSymbolAddress((void**)&d_a2b, g_a2b);
    int* d_b2a;    cudaGetSymbolAddress((void**)&d_b2a, g_b2a);
    int* d_b2revb; cudaGetSymbolAddress((void**)&d_b2revb, g_b2revb);
    int* d_mol;    cudaGetSymbolAddress((void**)&d_mol, g_mol);
    float* d_inp;  cudaGetSymbolAddress((void**)&d_inp, g_inp);
    float* d_msgA; cudaGetSymbolAddress((void**)&d_msgA, g_msgA);
    float* d_msgB; cudaGetSymbolAddress((void**)&d_msgB, g_msgB);
    float* d_amsg; cudaGetSymbolAddress((void**)&d_amsg, g_amsg);
    float* d_ah;   cudaGetSymbolAddress((void**)&d_ah, g_ah);
    unsigned short* d_Wi2; cudaGetSymbolAddress((void**)&d_Wi2, g_Wi2);
    unsigned short* d_Wh2; cudaGetSymbolAddress((void**)&d_Wh2, g_Wh2);
    unsigned short* d_Wo2; cudaGetSymbolAddress((void**)&d_Wo2, g_Wo2);
    unsigned short* d_pA;  cudaGetSymbolAddress((void**)&d_pA, g_pA);

    // 1) canonicalize indices
    reset_flags_kernel<<<1, 32>>>();
    scan_dtype_kernel<<<(NA * MAXNB + 255) / 256, 256>>>((const unsigned*)a2b, NA * MAXNB, 0);
    scan_dtype_kernel<<<(NBOND + 255) / 256, 256>>>((const unsigned*)b2a, NBOND, 1);
    scan_dtype_kernel<<<(NBOND + 255) / 256, 256>>>((const unsigned*)b2revb, NBOND, 2);
    scan_dtype_kernel<<<(NA + 255) / 256, 256>>>((const unsigned*)mol, NA, 3);
    convert_idx_kernel<<<(NA * MAXNB + 255) / 256, 256>>>(a2b, d_a2b, NA * MAXNB, 0);
    convert_idx_kernel<<<(NBOND + 255) / 256, 256>>>(b2a, d_b2a, NBOND, 1);
    convert_idx_kernel<<<(NBOND + 255) / 256, 256>>>(b2revb, d_b2revb, NBOND, 2);
    convert_idx_kernel<<<(NA + 255) / 256, 256>>>(mol, d_mol, NA, 3);

    // 2) pack weights
    conv_w_kernel<<<(512 * KP_WI + 255) / 256, 256>>>(W_i, d_Wi2, BF, KP_WI);
    conv_w_kernel<<<(512 * KP_WH + 255) / 256, 256>>>(W_h, d_Wh2, HID, KP_WH);
    conv_w_kernel<<<(512 * KP_WO + 255) / 256, 256>>>(W_o, d_Wo2, AF + HID, KP_WO);

    const int mtiles_b = (NBOND + 127) / 128;
    const int mtiles_a = (NA + 127) / 128;
    const int gthreads = 256;
    const int gblocks_a = (NA * (HID / 4) + gthreads - 1) / gthreads;

    // 3) inp = f_bonds @ W_i^T ; msg = relu(inp)
    pack_a_kernel<<<(NBOND * (KP_WI / 8) + 255) / 256, 256>>>(
        0, f_bonds, BF, BF, nullptr, d_pA, KP_WI, NBOND);
    mma_gemm_kernel<<<dim3(4, mtiles_b), 256>>>(
        d_pA, d_Wi2, KP_WI, KP_WI / 16, nullptr, nullptr, d_inp, 0, d_msgA, NBOND);

    // 4) message passing: gather + fused (update ∘ GEMM)
    float* cur = d_msgA;
    float* alt = d_msgB;
    for (int it = 0; it < 4; it++) {
        gather_sum_kernel<<<gblocks_a, gthreads>>>(cur, d_amsg);
        mma_gemm_fused_kernel<<<dim3(4, mtiles_b), 256>>>(
            d_amsg, cur, d_b2a, d_b2revb, d_Wh2, d_inp, alt);
        float* t = cur; cur = alt; alt = t;
    }

    // 5) final gather + output GEMM (concat packed)
    gather_sum_kernel<<<gblocks_a, gthreads>>>(cur, d_amsg);
    pack_a_kernel<<<(NA * (KP_WO / 8) + 255) / 256, 256>>>(
        2, f_atoms, AF, AF + HID, d_amsg, d_pA, KP_WO, NA);
    mma_gemm_kernel<<<dim3(4, mtiles_a), 256>>>(
        d_pA, d_Wo2, KP_WO, KP_WO / 16, nullptr, b_o, d_ah, 1, nullptr, NA);

    // 6) per-molecule mean pooling
    pool_zero_kernel<<<(NM * HID + 255) / 256, 256>>>();
    pool_sum_kernel<<<gblocks_a, gthreads>>>(d_ah);
    pool_count_kernel<<<(NA + 255) / 256, 256>>>();
    finalize_kernel<<<(NM * HID + 255) / 256, 256>>>(out);
}

// round 9
// speedup vs baseline: 2.4934x; 1.0787x over previous
#include <cuda_runtime.h>
#include <cuda_bf16.h>
#include <cstdint>

#define NA 60000
#define NBOND 120000
#define MAXNB 6
#define HID 512
#define AF 133
#define BF 147
#define NM 512

#define KP_WI 160
#define KP_WH 512
#define KP_WO 656

// ---------------- scratch (device globals) -----------------------------------
__device__ float g_inp[(size_t)NBOND * HID];
__device__ float g_msgA[(size_t)NBOND * HID];
__device__ float g_msgB[(size_t)NBOND * HID];
__device__ float g_amsg[(size_t)NA * HID];
__device__ float g_ah[(size_t)NA * HID];
__device__ float g_sums[NM * HID];
__device__ float g_cnt[NM];
__device__ int   g_a2b[NA * MAXNB];
__device__ int   g_b2a[NBOND];
__device__ int   g_b2revb[NBOND];
__device__ int   g_mol[NA];
__device__ int   g_any32[4];          // zero-init; monotone OR (graph-replay safe)
__device__ unsigned short g_Wi2[512 * KP_WI * 2];
__device__ unsigned short g_Wh2[512 * KP_WH * 2];
__device__ unsigned short g_Wo2[512 * KP_WO * 2];
__device__ unsigned short g_pA[(size_t)NA * KP_WO * 2];

// ---------------- helpers -----------------------------------------------------
__device__ __forceinline__ uint32_t smem_u32(const void* p) {
    uint32_t a;
    asm("{ .reg .u64 t; cvta.to.shared.u64 t, %1; cvt.u32.u64 %0, t; }" : "=r"(a) : "l"(p));
    return a;
}
__device__ __forceinline__ void ldm_x4(uint32_t* r, uint32_t addr) {
    asm volatile("ldmatrix.sync.aligned.m8n8.x4.shared.b16 {%0,%1,%2,%3}, [%4];"
                 : "=r"(r[0]), "=r"(r[1]), "=r"(r[2]), "=r"(r[3]) : "r"(addr));
}
__device__ __forceinline__ void mma_bf16(float* c, const uint32_t* a, uint32_t b0, uint32_t b1) {
    asm volatile("mma.sync.aligned.m16n8k16.row.col.f32.bf16.bf16.f32 "
                 "{%0,%1,%2,%3}, {%4,%5,%6,%7}, {%8,%9}, {%0,%1,%2,%3};"
                 : "+f"(c[0]), "+f"(c[1]), "+f"(c[2]), "+f"(c[3])
                 : "r"(a[0]), "r"(a[1]), "r"(a[2]), "r"(a[3]), "r"(b0), "r"(b1));
}
__device__ __forceinline__ void cp16(uint32_t dst, const void* src, int valid) {
    int sz = valid ? 16 : 0;
    asm volatile("cp.async.cg.shared.global [%0], [%1], 16, %2;"
                 :: "r"(dst), "l"(src), "r"(sz) : "memory");
}
__device__ __forceinline__ uint32_t pack2(float a, float b) {
    __nv_bfloat16 ha = __float2bfloat16(a), hb = __float2bfloat16(b);
    return (uint32_t)__bfloat16_as_ushort(ha) | ((uint32_t)__bfloat16_as_ushort(hb) << 16);
}

// ---------------- merged index scan / convert --------------------------------
#define N0 (NA * MAXNB)
#define N1 NBOND
#define N2 NBOND
#define N3 NA
#define NTOT (N0 + N1 + N2 + N3)

__global__ void scan_all_kernel(const unsigned* a2b, const unsigned* b2a,
                                const unsigned* b2revb, const unsigned* mol) {
    int idx = blockIdx.x * blockDim.x + threadIdx.x;
    if (idx >= NTOT) return;
    const unsigned* p; int i, fi;
    if (idx < N0)                { p = a2b;    i = idx;             fi = 0; }
    else if (idx < N0 + N1)      { p = b2a;    i = idx - N0;        fi = 1; }
    else if (idx < N0 + N1 + N2) { p = b2revb; i = idx - N0 - N1;   fi = 2; }
    else                         { p = mol;    i = idx - N0 - N1 - N2; fi = 3; }
    if ((i & 1) && p[i] != 0u) atomicOr(&g_any32[fi], 1);
}

__global__ void convert_all_kernel(const void* a2b, const void* b2a,
                                   const void* b2revb, const void* mol) {
    int idx = blockIdx.x * blockDim.x + threadIdx.x;
    if (idx >= NTOT) return;
    const void* p; int i, fi; int* dst;
    if (idx < N0)                { p = a2b;    i = idx;                fi = 0; dst = g_a2b; }
    else if (idx < N0 + N1)      { p = b2a;    i = idx - N0;           fi = 1; dst = g_b2a; }
    else if (idx < N0 + N1 + N2) { p = b2revb; i = idx - N0 - N1;      fi = 2; dst = g_b2revb; }
    else                         { p = mol;    i = idx - N0 - N1 - N2; fi = 3; dst = g_mol; }
    if (g_any32[fi]) dst[i] = ((const int*)p)[i];
    else             dst[i] = (int)((const long long*)p)[i];
}

// ---------------- element workers ---------------------------------------------
__device__ __forceinline__ void conv_w_elem(const float* __restrict__ W,
                                            unsigned short* __restrict__ Wp,
                                            int K, int KP, int idx) {
    int n = idx / KP, k = idx - n * KP;
    float v = (k < K) ? W[(size_t)n * K + k] : 0.f;
    __nv_bfloat16 hb = __float2bfloat16(v);
    float r = v - __bfloat162float(hb);
    __nv_bfloat16 lb = __float2bfloat16(r);
    size_t base = (size_t)n * KP * 2 + (size_t)(k >> 4) * 32 + (k & 15);
    Wp[base]      = __bfloat16_as_ushort(hb);
    Wp[base + 16] = __bfloat16_as_ushort(lb);
}

__device__ __forceinline__ void pack_row8(const float v[8], unsigned short* out,
                                          int KP, int row, int kb) {
    float lo[8];
    #pragma unroll
    for (int e = 0; e < 8; e++)
        lo[e] = v[e] - __bfloat162float(__float2bfloat16(v[e]));
    uint4 hq = make_uint4(pack2(v[0], v[1]), pack2(v[2], v[3]), pack2(v[4], v[5]), pack2(v[6], v[7]));
    uint4 lq = make_uint4(pack2(lo[0], lo[1]), pack2(lo[2], lo[3]), pack2(lo[4], lo[5]), pack2(lo[6], lo[7]));
    int c = kb >> 4, c2 = (kb >> 3) & 1;
    char* rb_ = (char*)(out + (size_t)row * KP * 2) + c * 64 + c2 * 16;
    *(uint4*)(rb_)      = hq;
    *(uint4*)(rb_ + 32) = lq;
}

// ---------------- prep: weight packs + W_i A pack, one launch ----------------
#define NWI (512 * KP_WI)
#define NWH (512 * KP_WH)
#define NWO (512 * KP_WO)
#define NPK (NBOND * (KP_WI / 8))
#define NPREP (NWI + NWH + NWO + NPK)

__global__ void prep_kernel(const float* __restrict__ Wi, const float* __restrict__ Wh,
                            const float* __restrict__ Wo, const float* __restrict__ f_bonds) {
    int idx = blockIdx.x * blockDim.x + threadIdx.x;
    if (idx >= NPREP) return;
    if (idx < NWI) { conv_w_elem(Wi, g_Wi2, BF, KP_WI, idx); return; }
    idx -= NWI;
    if (idx < NWH) { conv_w_elem(Wh, g_Wh2, HID, KP_WH, idx); return; }
    idx -= NWH;
    if (idx < NWO) { conv_w_elem(Wo, g_Wo2, AF + HID, KP_WO, idx); return; }
    idx -= NWO;
    // pack f_bonds rows into g_pA
    const int t8n = KP_WI / 8;
    int row = idx / t8n;
    int kb = (idx - row * t8n) * 8;
    float v[8];
    const float* r = f_bonds + (size_t)row * BF;
    #pragma unroll
    for (int e = 0; e < 8; e++)
        v[e] = (kb + e < BF) ? r[kb + e] : 0.f;
    pack_row8(v, g_pA, KP_WI, row, kb);
}

// ---------------- W_o A pack (concat f_atoms | amsg) -------------------------
__global__ void pack_awo_kernel(const float* __restrict__ f_atoms,
                                const float* __restrict__ amsg) {
    const int t8n = KP_WO / 8;
    int idx = blockIdx.x * blockDim.x + threadIdx.x;
    if (idx >= NA * t8n) return;
    int row = idx / t8n;
    int kb = (idx - row * t8n) * 8;
    float v[8];
    #pragma unroll
    for (int e = 0; e < 8; e++) {
        int k = kb + e;
        float x = 0.f;
        if (k < AF) x = f_atoms[(size_t)row * AF + k];
        else if (k < AF + HID) x = amsg[(size_t)row * HID + (k - AF)];
        v[e] = x;
    }
    pack_row8(v, g_pA, KP_WO, row, kb);
}

// ---------------- shared GEMM geometry ---------------------------------------
#define ROWB 80
#define BUFB (128 * ROWB)

// ---------------- packed-A GEMM (W_i / W_o paths) ----------------------------
__global__ __launch_bounds__(256, 2)
void mma_gemm_kernel(const unsigned short* __restrict__ pA,
                     const unsigned short* __restrict__ Wp, int KP, int NC,
                     const float* __restrict__ bias,
                     float* __restrict__ out1, int relu1,
                     float* __restrict__ out2, int M) {
    __shared__ char smA[2][BUFB];
    __shared__ char smB[2][BUFB];
    const uint32_t aBase = smem_u32(&smA[0][0]);
    const uint32_t bBase = smem_u32(&smB[0][0]);

    const int tid = threadIdx.x;
    const int wid = tid >> 5, lane = tid & 31;
    const int bm = blockIdx.y * 128;
    const int bn = blockIdx.x * 128;
    const int wm = (wid >> 2) * 64;
    const int wn = (wid & 3) * 32;

    const int rL = tid >> 1;
    const int c2 = tid & 1;
    const int gmL = bm + rL;
    const int okA = gmL < M;
    const char* gA = (const char*)(pA + (size_t)gmL * KP * 2) + c2 * 32;
    const char* gB = (const char*)(Wp + (size_t)(bn + rL) * KP * 2) + c2 * 32;
    const uint32_t sA = aBase + rL * ROWB + c2 * 32;
    const uint32_t sB = bBase + rL * ROWB + c2 * 32;

    float acc[4][4][4];
    #pragma unroll
    for (int i = 0; i < 4; i++)
        #pragma unroll
        for (int j = 0; j < 4; j++)
            #pragma unroll
            for (int e = 0; e < 4; e++) acc[i][j][e] = 0.f;

    auto prefetch = [&](int c, int buf) {
        const char* a = gA + (size_t)c * 64;
        const char* b = gB + (size_t)c * 64;
        cp16(sA + buf * BUFB, a, okA);
        cp16(sA + buf * BUFB + 16, a + 16, okA);
        cp16(sB + buf * BUFB, b, 1);
        cp16(sB + buf * BUFB + 16, b + 16, 1);
        asm volatile("cp.async.commit_group;" ::: "memory");
    };

    const uint32_t aAddr = aBase + (wm + (lane & 15)) * ROWB + (lane >> 4) * 16;
    const uint32_t bAddr = bBase + (wn + (lane & 7) + (lane >= 16 ? 8 : 0)) * ROWB
                                 + ((lane >> 3) & 1) * 16;

    prefetch(0, 0);
    for (int c = 0; c < NC; c++) {
        int buf = c & 1;
        if (c + 1 < NC) {
            prefetch(c + 1, buf ^ 1);
            asm volatile("cp.async.wait_group 1;" ::: "memory");
        } else {
            asm volatile("cp.async.wait_group 0;" ::: "memory");
        }
        __syncthreads();

        uint32_t aH[4][4], aL[4][4], bH[2][4], bL[2][4];
        #pragma unroll
        for (int i = 0; i < 4; i++) {
            ldm_x4(aH[i], aAddr + buf * BUFB + i * 16 * ROWB);
            ldm_x4(aL[i], aAddr + buf * BUFB + i * 16 * ROWB + 32);
        }
        #pragma unroll
        for (int p = 0; p < 2; p++) {
            ldm_x4(bH[p], bAddr + buf * BUFB + p * 16 * ROWB);
            ldm_x4(bL[p], bAddr + buf * BUFB + p * 16 * ROWB + 32);
        }
        #pragma unroll
        for (int i = 0; i < 4; i++)
            #pragma unroll
            for (int j = 0; j < 4; j++) {
                mma_bf16(acc[i][j], aH[i], bH[j >> 1][(j & 1) * 2], bH[j >> 1][(j & 1) * 2 + 1]);
                mma_bf16(acc[i][j], aL[i], bH[j >> 1][(j & 1) * 2], bH[j >> 1][(j & 1) * 2 + 1]);
                mma_bf16(acc[i][j], aH[i], bL[j >> 1][(j & 1) * 2], bL[j >> 1][(j & 1) * 2 + 1]);
            }
        __syncthreads();
    }

    const int g = lane >> 2, tg = lane & 3;
    #pragma unroll
    for (int i = 0; i < 4; i++) {
        #pragma unroll
        for (int h = 0; h < 2; h++) {
            int gm = bm + wm + i * 16 + g + h * 8;
            if (gm >= M) continue;
            #pragma unroll
            for (int j = 0; j < 4; j++) {
                int gn = bn + wn + j * 8 + tg * 2;
                float v0 = acc[i][j][h * 2 + 0];
                float v1 = acc[i][j][h * 2 + 1];
                if (bias) {
                    float2 b = *(const float2*)(bias + gn);
                    v0 += b.x; v1 += b.y;
                }
                float r0 = fmaxf(v0, 0.f), r1 = fmaxf(v1, 0.f);
                float2 o = relu1 ? make_float2(r0, r1) : make_float2(v0, v1);
                *(float2*)(out1 + (size_t)gm * HID + gn) = o;
                if (out2) *(float2*)(out2 + (size_t)gm * HID + gn) = make_float2(r0, r1);
            }
        }
    }
}

// ---------------- fused W_h GEMM, 3-stage pipeline ---------------------------
// A = amsg[b2a[m]] - msg[b2revb[m]]; msg_new = relu(inp + A @ W_h^T).
// LDGs for chunk c+2 issued BEFORE compute(c); split/STS after.
#define FSM_BYTES (6 * BUFB)

__global__ __launch_bounds__(256, 2)
void mma_gemm_fused_kernel(const float* __restrict__ amsg,
                           const float* __restrict__ msg,
                           const int* __restrict__ b2a,
                           const int* __restrict__ b2revb,
                           const unsigned short* __restrict__ Wp,
                           const float* __restrict__ inp,
                           float* __restrict__ out1) {
    const int NC = KP_WH / 16;   // 32
    extern __shared__ char dyn[];
    const uint32_t aBase = smem_u32(dyn);
    const uint32_t bBase = aBase + 3 * BUFB;

    const int tid = threadIdx.x;
    const int wid = tid >> 5, lane = tid & 31;
    const int bm = blockIdx.y * 128;
    const int bn = blockIdx.x * 128;
    const int wm = (wid >> 2) * 64;
    const int wn = (wid & 3) * 32;

    const int rL = tid >> 1;
    const int c2 = tid & 1;
    const int gmL = bm + rL;
    const int okA = gmL < NBOND;
    const int sa = okA ? b2a[gmL] : 0;
    const int rb = okA ? b2revb[gmL] : 0;
    const char* gU = (const char*)(amsg + (size_t)sa * HID) + c2 * 32;
    const char* gW = (const char*)(msg + (size_t)rb * HID) + c2 * 32;
    const char* gB = (const char*)(Wp + (size_t)(bn + rL) * KP_WH * 2) + c2 * 32;
    const uint32_t sB = bBase + rL * ROWB + c2 * 32;

    float acc[4][4][4];
    #pragma unroll
    for (int i = 0; i < 4; i++)
        #pragma unroll
        for (int j = 0; j < 4; j++)
            #pragma unroll
            for (int e = 0; e < 4; e++) acc[i][j][e] = 0.f;

    float4 u0, u1, w0, w1;
    auto loadA_issue = [&](int c) {
        if (okA) {
            const char* u = gU + (size_t)c * 64;
            const char* w = gW + (size_t)c * 64;
            u0 = *(const float4*)(u);
            u1 = *(const float4*)(u + 16);
            w0 = *(const float4*)(w);
            w1 = *(const float4*)(w + 16);
        }
    };
    auto storeA = [&](int s) {
        float v[8];
        if (okA) {
            v[0] = u0.x - w0.x; v[1] = u0.y - w0.y; v[2] = u0.z - w0.z; v[3] = u0.w - w0.w;
            v[4] = u1.x - w1.x; v[5] = u1.y - w1.y; v[6] = u1.z - w1.z; v[7] = u1.w - w1.w;
        } else {
            #pragma unroll
            for (int e = 0; e < 8; e++) v[e] = 0.f;
        }
        float lo[8];
        #pragma unroll
        for (int e = 0; e < 8; e++)
            lo[e] = v[e] - __bfloat162float(__float2bfloat16(v[e]));
        uint4 hq = make_uint4(pack2(v[0], v[1]), pack2(v[2], v[3]), pack2(v[4], v[5]), pack2(v[6], v[7]));
        uint4 lq = make_uint4(pack2(lo[0], lo[1]), pack2(lo[2], lo[3]), pack2(lo[4], lo[5]), pack2(lo[6], lo[7]));
        char* ar = dyn + s * BUFB + rL * ROWB;
        *(uint4*)(ar + c2 * 16)      = hq;
        *(uint4*)(ar + 32 + c2 * 16) = lq;
    };
    auto prefetchB = [&](int c, int s) {
        const char* b = gB + (size_t)c * 64;
        cp16(sB + s * BUFB, b, 1);
        cp16(sB + s * BUFB + 16, b + 16, 1);
        asm volatile("cp.async.commit_group;" ::: "memory");
    };

    const uint32_t aAddr = aBase + (wm + (lane & 15)) * ROWB + (lane >> 4) * 16;
    const uint32_t bAddr = bBase + (wn + (lane & 7) + (lane >= 16 ? 8 : 0)) * ROWB
                                 + ((lane >> 3) & 1) * 16;

    // prologue: stages 0,1
    loadA_issue(0); storeA(0); prefetchB(0, 0);
    loadA_issue(1); storeA(1); prefetchB(1, 1);

    int buf = 0;
    #pragma unroll 1
    for (int c = 0; c < NC; c++) {
        if (c + 1 < NC) { asm volatile("cp.async.wait_group 1;" ::: "memory"); }
        else            { asm volatile("cp.async.wait_group 0;" ::: "memory"); }
        __syncthreads();

        int nb = buf + 2; if (nb >= 3) nb -= 3;
        if (c + 2 < NC) loadA_issue(c + 2);     // LDGs in flight during compute

        uint32_t af[4][4], bH[2][4], bL[2][4];
        #pragma unroll
        for (int p = 0; p < 2; p++) {
            ldm_x4(bH[p], bAddr + buf * BUFB + p * 16 * ROWB);
            ldm_x4(bL[p], bAddr + buf * BUFB + p * 16 * ROWB + 32);
        }
        #pragma unroll
        for (int i = 0; i < 4; i++)
            ldm_x4(af[i], aAddr + buf * BUFB + i * 16 * ROWB);        // aH
        #pragma unroll
        for (int i = 0; i < 4; i++)
            #pragma unroll
            for (int j = 0; j < 4; j++) {
                mma_bf16(acc[i][j], af[i], bH[j >> 1][(j & 1) * 2], bH[j >> 1][(j & 1) * 2 + 1]);
                mma_bf16(acc[i][j], af[i], bL[j >> 1][(j & 1) * 2], bL[j >> 1][(j & 1) * 2 + 1]);
            }
        #pragma unroll
        for (int i = 0; i < 4; i++)
            ldm_x4(af[i], aAddr + buf * BUFB + i * 16 * ROWB + 32);   // aL
        #pragma unroll
        for (int i = 0; i < 4; i++)
            #pragma unroll
            for (int j = 0; j < 4; j++)
                mma_bf16(acc[i][j], af[i], bH[j >> 1][(j & 1) * 2], bH[j >> 1][(j & 1) * 2 + 1]);

        if (c + 2 < NC) { storeA(nb); prefetchB(c + 2, nb); }
        buf++; if (buf == 3) buf = 0;
    }

    // epilogue: relu(inp + acc)
    const int g = lane >> 2, tg = lane & 3;
    #pragma unroll
    for (int i = 0; i < 4; i++) {
        #pragma unroll
        for (int h = 0; h < 2; h++) {
            int gm = bm + wm + i * 16 + g + h * 8;
            if (gm >= NBOND) continue;
            #pragma unroll
            for (int j = 0; j < 4; j++) {
                int gn = bn + wn + j * 8 + tg * 2;
                float2 a = *(const float2*)(inp + (size_t)gm * HID + gn);
                float v0 = acc[i][j][h * 2 + 0] + a.x;
                float v1 = acc[i][j][h * 2 + 1] + a.y;
                *(float2*)(out1 + (size_t)gm * HID + gn) =
                    make_float2(fmaxf(v0, 0.f), fmaxf(v1, 0.f));
            }
        }
    }
}

// ---------------- gather ------------------------------------------------------
__global__ void gather_sum_kernel(const float* __restrict__ msg,
                                  float* __restrict__ amsg) {
    int idx = blockIdx.x * blockDim.x + threadIdx.x;
    const int h4 = HID / 4;
    if (idx >= NA * h4) return;
    int a = idx / h4;
    int h = (idx - a * h4) * 4;
    float4 acc = make_float4(0.f, 0.f, 0.f, 0.f);
    #pragma unroll
    for (int j = 0; j < MAXNB; j++) {
        int b = g_a2b[a * MAXNB + j];
        float4 v = *(const float4*)(msg + (size_t)b * HID + h);
        acc.x += v.x; acc.y += v.y; acc.z += v.z; acc.w += v.w;
    }
    *(float4*)(amsg + (size_t)a * HID + h) = acc;
}

// ---------------- pooling -----------------------------------------------------
__global__ void pool_zero_kernel() {
    int i = blockIdx.x * blockDim.x + threadIdx.x;
    if (i < NM * HID) g_sums[i] = 0.f;
    if (i < NM) g_cnt[i] = 0.f;
}
__global__ void pool_sum_kernel(const float* __restrict__ ah) {
    int idx = blockIdx.x * blockDim.x + threadIdx.x;
    const int h4 = HID / 4;
    if (idx >= NA * h4) return;
    int a = idx / h4;
    int h = (idx - a * h4) * 4;
    int m = g_mol[a];
    float4 v = *(const float4*)(ah + (size_t)a * HID + h);
    float* dst = g_sums + (size_t)m * HID + h;
    atomicAdd(dst + 0, v.x);
    atomicAdd(dst + 1, v.y);
    atomicAdd(dst + 2, v.z);
    atomicAdd(dst + 3, v.w);
}
__global__ void pool_count_kernel() {
    int a = blockIdx.x * blockDim.x + threadIdx.x;
    if (a >= NA) return;
    atomicAdd(&g_cnt[g_mol[a]], 1.f);
}
__global__ void finalize_kernel(float* __restrict__ out) {
    int i = blockIdx.x * blockDim.x + threadIdx.x;
    if (i >= NM * HID) return;
    float c = g_cnt[i / HID];
    out[i] = g_sums[i] / fmaxf(c, 1.f);
}

// ---------------- launch ------------------------------------------------------
extern "C" void kernel_launch(void* const* d_in, const int* in_sizes, int n_in,
                              void* d_out, int out_size) {
    const float* f_atoms = (const float*)d_in[0];
    const float* f_bonds = (const float*)d_in[1];
    const float* W_i     = (const float*)d_in[2];
    const float* W_h     = (const float*)d_in[3];
    const float* W_o     = (const float*)d_in[4];
    const float* b_o     = (const float*)d_in[5];
    const void*  a2b     = d_in[6];
    const void*  b2a     = d_in[7];
    const void*  b2revb  = d_in[8];
    const void*  mol     = d_in[9];
    float* out = (float*)d_out;

    int* d_b2a;    cudaGetSymbolAddress((void**)&d_b2a, g_b2a);
    int* d_b2revb; cudaGetSymbolAddress((void**)&d_b2revb, g_b2revb);
    float* d_inp;  cudaGetSymbolAddress((void**)&d_inp, g_inp);
    float* d_msgA; cudaGetSymbolAddress((void**)&d_msgA, g_msgA);
    float* d_msgB; cudaGetSymbolAddress((void**)&d_msgB, g_msgB);
    float* d_amsg; cudaGetSymbolAddress((void**)&d_amsg, g_amsg);
    float* d_ah;   cudaGetSymbolAddress((void**)&d_ah, g_ah);
    unsigned short* d_Wi2; cudaGetSymbolAddress((void**)&d_Wi2, g_Wi2);
    unsigned short* d_Wh2; cudaGetSymbolAddress((void**)&d_Wh2, g_Wh2);
    unsigned short* d_Wo2; cudaGetSymbolAddress((void**)&d_Wo2, g_Wo2);
    unsigned short* d_pA;  cudaGetSymbolAddress((void**)&d_pA, g_pA);

    static int init_done = 0;
    if (!init_done) {
        cudaFuncSetAttribute(mma_gemm_fused_kernel,
                             cudaFuncAttributeMaxDynamicSharedMemorySize, FSM_BYTES);
        init_done = 1;
    }

    const int mtiles_b = (NBOND + 127) / 128;
    const int mtiles_a = (NA + 127) / 128;
    const int gthreads = 256;
    const int gblocks_a = (NA * (HID / 4) + gthreads - 1) / gthreads;

    // 0: index dtype scan (flags zero-init; monotone -> replay-safe)
    scan_all_kernel<<<(NTOT + 255) / 256, 256>>>(
        (const unsigned*)a2b, (const unsigned*)b2a, (const unsigned*)b2revb, (const unsigned*)mol);
    // 1: convert all indices
    convert_all_kernel<<<(NTOT + 255) / 256, 256>>>(a2b, b2a, b2revb, mol);
    // 2: weight packs + W_i A pack
    prep_kernel<<<(NPREP + 255) / 256, 256>>>(W_i, W_h, W_o, f_bonds);
    // 3: inp = f_bonds @ W_i^T ; msg = relu(inp)
    mma_gemm_kernel<<<dim3(4, mtiles_b), 256>>>(
        d_pA, d_Wi2, KP_WI, KP_WI / 16, nullptr, d_inp, 0, d_msgA, NBOND);

    // 4..: message passing
    float* cur = d_msgA;
    float* alt = d_msgB;
    for (int it = 0; it < 4; it++) {
        gather_sum_kernel<<<gblocks_a, gthreads>>>(cur, d_amsg);
        mma_gemm_fused_kernel<<<dim3(4, mtiles_b), 256, FSM_BYTES>>>(
            d_amsg, cur, d_b2a, d_b2revb, d_Wh2, d_inp, alt);
        float* t = cur; cur = alt; alt = t;
    }

    // final gather + W_o GEMM
    gather_sum_kernel<<<gblocks_a, gthreads>>>(cur, d_amsg);
    pack_awo_kernel<<<(NA * (KP_WO / 8) + 255) / 256, 256>>>(f_atoms, d_amsg);
    mma_gemm_kernel<<<dim3(4, mtiles_a), 256>>>(
        d_pA, d_Wo2, KP_WO, KP_WO / 16, b_o, d_ah, 1, nullptr, NA);

    // pooling
    pool_zero_kernel<<<(NM * HID + 255) / 256, 256>>>();
    pool_sum_kernel<<<gblocks_a, gthreads>>>(d_ah);
    pool_count_kernel<<<(NA + 255) / 256, 256>>>();
    finalize_kernel<<<(NM * HID + 255) / 256, 256>>>(out);
}